// round 4
// baseline (speedup 1.0000x reference)
#include <cuda_runtime.h>

// ---------------------------------------------------------------------------
// SpatialWindowSelfAttention: b=2, h=w=256, C=256, heads=8, head_dim=32,
// window 8x8 (ws=64). Fixed shapes from setup_inputs; h/w inputs (d_in[1],
// d_in[2]) are 256 and ignored (padding is a no-op since 256 % 8 == 0).
//
// Pipeline:
//   1) gemm_bias_kernel: qkv = x @ Wqkv^T + bqkv          [131072 x 768]
//   2) window_attn_kernel: per (window, head) attention, writes y in image
//      layout [b, H, W, C] so step 3 is a plain GEMM
//   3) gemm_bias_kernel: out = y @ Wp^T + bp              [131072 x 256]
// ---------------------------------------------------------------------------

#define K_DIM 256
#define BM 128
#define BN 128
#define BK 16
#define TM 8
#define TN 8

// Scratch (b=2 fixed by the problem instance)
__device__ float g_qkv[131072ull * 768];   // 384 MiB
__device__ float g_y  [131072ull * 256];   // 128 MiB

// ---------------------------------------------------------------------------
// Tiled fp32 GEMM with bias: C[m, n] = sum_k A[m,k] * W[n,k] + bias[n]
// A: [M, 256] row-major, W: [N, 256] row-major. BM=BN=128, BK=16,
// 256 threads, 8x8 register tile per thread.
// ---------------------------------------------------------------------------
__global__ __launch_bounds__(256) void gemm_bias_kernel(
    const float* __restrict__ A, const float* __restrict__ W,
    const float* __restrict__ bias, float* __restrict__ C, int N) {
    __shared__ __align__(16) float As[BK][BM + 4];   // row stride 132 floats = 528B (16B multiple)
    __shared__ __align__(16) float Bs[BK][BN + 4];

    const int tid = threadIdx.x;
    const int tx = tid & 15;         // 16 col-groups
    const int ty = tid >> 4;         // 16 row-groups
    const long rowBase = (long)blockIdx.y * BM;
    const int  colBase = blockIdx.x * BN;

    float acc[TM][TN];
#pragma unroll
    for (int i = 0; i < TM; i++)
#pragma unroll
        for (int j = 0; j < TN; j++) acc[i][j] = 0.0f;

    for (int k0 = 0; k0 < K_DIM; k0 += BK) {
        // Load A tile (128x16) and B tile (128x16): 512 float4 each,
        // 2 float4 per tensor per thread.
#pragma unroll
        for (int r = 0; r < 2; r++) {
            int q   = tid + r * 256;      // 0..511
            int row = q >> 2;             // 0..127
            int kq  = q & 3;              // quad within the 16-wide k slab
            float4 va = *(const float4*)(A + (rowBase + row) * K_DIM + k0 + kq * 4);
            As[kq * 4 + 0][row] = va.x;
            As[kq * 4 + 1][row] = va.y;
            As[kq * 4 + 2][row] = va.z;
            As[kq * 4 + 3][row] = va.w;
            float4 vb = *(const float4*)(W + (long)(colBase + row) * K_DIM + k0 + kq * 4);
            Bs[kq * 4 + 0][row] = vb.x;
            Bs[kq * 4 + 1][row] = vb.y;
            Bs[kq * 4 + 2][row] = vb.z;
            Bs[kq * 4 + 3][row] = vb.w;
        }
        __syncthreads();

#pragma unroll
        for (int kk = 0; kk < BK; kk++) {
            float a[TM], b[TN];
            float4 a0 = *(const float4*)&As[kk][ty * TM];
            float4 a1 = *(const float4*)&As[kk][ty * TM + 4];
            a[0] = a0.x; a[1] = a0.y; a[2] = a0.z; a[3] = a0.w;
            a[4] = a1.x; a[5] = a1.y; a[6] = a1.z; a[7] = a1.w;
            float4 b0 = *(const float4*)&Bs[kk][tx * TN];
            float4 b1 = *(const float4*)&Bs[kk][tx * TN + 4];
            b[0] = b0.x; b[1] = b0.y; b[2] = b0.z; b[3] = b0.w;
            b[4] = b1.x; b[5] = b1.y; b[6] = b1.z; b[7] = b1.w;
#pragma unroll
            for (int i = 0; i < TM; i++)
#pragma unroll
                for (int j = 0; j < TN; j++)
                    acc[i][j] = fmaf(a[i], b[j], acc[i][j]);
        }
        __syncthreads();
    }

    float bj[TN];
#pragma unroll
    for (int j = 0; j < TN; j++) bj[j] = bias[colBase + tx * TN + j];

#pragma unroll
    for (int i = 0; i < TM; i++) {
        long row = rowBase + ty * TM + i;
        float4 o0, o1;
        o0.x = acc[i][0] + bj[0]; o0.y = acc[i][1] + bj[1];
        o0.z = acc[i][2] + bj[2]; o0.w = acc[i][3] + bj[3];
        o1.x = acc[i][4] + bj[4]; o1.y = acc[i][5] + bj[5];
        o1.z = acc[i][6] + bj[6]; o1.w = acc[i][7] + bj[7];
        *(float4*)(C + row * N + colBase + tx * TN)     = o0;
        *(float4*)(C + row * N + colBase + tx * TN + 4) = o1;
    }
}

// ---------------------------------------------------------------------------
// Window attention. One block per (window, head): 64 tokens, head_dim 32.
// blockIdx.x = window * 8 + head. Windows ordered (b, wr, wc), 32x32 per img.
// Reads qkv [row, 768] (q|k|v packed), writes y in image layout [row, 256].
// ---------------------------------------------------------------------------
__global__ __launch_bounds__(256) void window_attn_kernel(
    const float* __restrict__ qkv, const float* __restrict__ bias_table,
    float* __restrict__ y) {
    const int head = blockIdx.x & 7;
    const int wi   = blockIdx.x >> 3;
    const int bimg = wi >> 10;          // 1024 windows per image
    const int widx = wi & 1023;
    const int wr   = widx >> 5;
    const int wc   = widx & 31;

    __shared__ float q_s[64][33];
    __shared__ float k_s[64][33];
    __shared__ float v_s[64][33];
    __shared__ float s_s[64][65];
    __shared__ float bias_s[225];

    const int tid = threadIdx.x;
    for (int i = tid; i < 225; i += 256) bias_s[i] = bias_table[i * 8 + head];

    const float scale = 0.17677669529663687f;   // 1/sqrt(32)

    // Load q,k,v tiles: 64 tokens x 32 dims each; 2 float4 per tensor/thread.
#pragma unroll
    for (int r = 0; r < 2; r++) {
        int q   = tid + r * 256;        // 0..511
        int tok = q >> 3;               // 0..63
        int dq  = (q & 7) * 4;          // 0,4,...,28
        long row = (long)bimg * 65536 + (long)(wr * 8 + (tok >> 3)) * 256 + wc * 8 + (tok & 7);
        const float* base = qkv + row * 768 + head * 32 + dq;
        float4 vq = *(const float4*)(base);
        float4 vk = *(const float4*)(base + 256);
        float4 vv = *(const float4*)(base + 512);
        q_s[tok][dq + 0] = vq.x * scale; q_s[tok][dq + 1] = vq.y * scale;
        q_s[tok][dq + 2] = vq.z * scale; q_s[tok][dq + 3] = vq.w * scale;
        k_s[tok][dq + 0] = vk.x; k_s[tok][dq + 1] = vk.y;
        k_s[tok][dq + 2] = vk.z; k_s[tok][dq + 3] = vk.w;
        v_s[tok][dq + 0] = vv.x; v_s[tok][dq + 1] = vv.y;
        v_s[tok][dq + 2] = vv.z; v_s[tok][dq + 3] = vv.w;
    }
    __syncthreads();

    // Scores: each thread computes a 4x4 block of the 64x64 score matrix.
    {
        const int qg = tid >> 4;    // 16 groups of 4 query rows
        const int kg = tid & 15;    // 16 groups of 4 key cols
        float acc[4][4];
#pragma unroll
        for (int i = 0; i < 4; i++)
#pragma unroll
            for (int j = 0; j < 4; j++) acc[i][j] = 0.0f;

#pragma unroll 4
        for (int d = 0; d < 32; d++) {
            float qv[4], kv[4];
#pragma unroll
            for (int i = 0; i < 4; i++) qv[i] = q_s[qg * 4 + i][d];
#pragma unroll
            for (int j = 0; j < 4; j++) kv[j] = k_s[kg * 4 + j][d];
#pragma unroll
            for (int i = 0; i < 4; i++)
#pragma unroll
                for (int j = 0; j < 4; j++)
                    acc[i][j] = fmaf(qv[i], kv[j], acc[i][j]);
        }
#pragma unroll
        for (int i = 0; i < 4; i++)
#pragma unroll
            for (int j = 0; j < 4; j++) {
                int qi = qg * 4 + i, ki = kg * 4 + j;
                int idx = ((qi >> 3) - (ki >> 3) + 7) * 15 + ((qi & 7) - (ki & 7) + 7);
                s_s[qi][ki] = acc[i][j] + bias_s[idx];
            }
    }
    __syncthreads();

    // Softmax per row (64 rows, one thread each).
    if (tid < 64) {
        float m = -1e30f;
#pragma unroll 8
        for (int k = 0; k < 64; k++) m = fmaxf(m, s_s[tid][k]);
        float sum = 0.0f;
#pragma unroll 8
        for (int k = 0; k < 64; k++) {
            float e = __expf(s_s[tid][k] - m);
            s_s[tid][k] = e;
            sum += e;
        }
        float inv = 1.0f / sum;
#pragma unroll 8
        for (int k = 0; k < 64; k++) s_s[tid][k] *= inv;
    }
    __syncthreads();

    // y = P @ V : thread handles 8 query rows at one dim d.
    {
        const int d  = tid & 31;
        const int q0 = (tid >> 5) * 8;
        float out[8];
#pragma unroll
        for (int r = 0; r < 8; r++) out[r] = 0.0f;
#pragma unroll 4
        for (int ki = 0; ki < 64; ki++) {
            float vv = v_s[ki][d];
#pragma unroll
            for (int r = 0; r < 8; r++)
                out[r] = fmaf(s_s[q0 + r][ki], vv, out[r]);
        }
#pragma unroll
        for (int r = 0; r < 8; r++) {
            int tok = q0 + r;
            long row = (long)bimg * 65536 + (long)(wr * 8 + (tok >> 3)) * 256 + wc * 8 + (tok & 7);
            y[row * 256 + head * 32 + d] = out[r];
        }
    }
}

extern "C" void kernel_launch(void* const* d_in, const int* in_sizes, int n_in,
                              void* d_out, int out_size) {
    const float* x          = (const float*)d_in[0];
    // d_in[1] = h (256), d_in[2] = w (256): fixed for this instance, unused.
    const float* wqkv_w     = (const float*)d_in[3];
    const float* wqkv_b     = (const float*)d_in[4];
    const float* wp_w       = (const float*)d_in[5];
    const float* wp_b       = (const float*)d_in[6];
    const float* bias_table = (const float*)d_in[7];
    float* out = (float*)d_out;

    const int M = in_sizes[0] / K_DIM;         // 131072 rows (b*h*w)

    float *qkv_ptr, *y_ptr;
    cudaGetSymbolAddress((void**)&qkv_ptr, g_qkv);
    cudaGetSymbolAddress((void**)&y_ptr,   g_y);

    // 1) QKV projection: [M,256] @ [768,256]^T + b -> [M,768]
    {
        dim3 grid(768 / BN, M / BM);
        gemm_bias_kernel<<<grid, 256>>>(x, wqkv_w, wqkv_b, qkv_ptr, 768);
    }

    // 2) Window attention: (M/65536)*1024 windows * 8 heads blocks
    {
        int nblocks = (M / 65536) * 1024 * 8;
        window_attn_kernel<<<nblocks, 256>>>(qkv_ptr, bias_table, y_ptr);
    }

    // 3) Output projection: [M,256] @ [256,256]^T + b -> [M,256]
    {
        dim3 grid(256 / BN, M / BM);
        gemm_bias_kernel<<<grid, 256>>>(y_ptr, wp_w, wp_b, out, 256);
    }
}

// round 6
// speedup vs baseline: 1.8283x; 1.8283x over previous
#include <cuda_runtime.h>
#include <cuda_bf16.h>
#include <cstdint>
#include <cstring>

// ---------------------------------------------------------------------------
// SpatialWindowSelfAttention on GB300 (sm_103a), b=2, h=w=256, C=256,
// heads=8, head_dim=32, window 8x8 (ws=64).
//
//  1) split_weights_kernel : Wqkv/Wp fp32 -> (hi, lo) bf16 pairs
//  2) mma_gemm_kernel (QKV): ldmatrix + mma.sync bf16x3, C = A @ W^T + bias
//  3) window_attn_kernel   : per (window, head) attention
//  4) mma_gemm_kernel (proj)
//
// bf16x3: A = Ah + Al, W = Wh + Wl; D += Ah*Wh + Ah*Wl + Al*Wh with fp32
// accumulation -> rel_err ~1e-5 << 1e-3. mma.sync/ldmatrix are baseline PTX
// (sm_80+), so both the sm_103a and the plain compute_103 fatbin targets
// compile (tcgen05 does not survive the compute_103 pass — R4 post-mortem).
// ---------------------------------------------------------------------------

#define K_DIM 256

// Scratch (b=2 fixed by the problem instance)
__device__ float g_qkv[131072ull * 768];            // 384 MiB
__device__ float g_y  [131072ull * 256];            // 128 MiB
__device__ __nv_bfloat16 g_wqkv_h[768 * 256];
__device__ __nv_bfloat16 g_wqkv_l[768 * 256];
__device__ __nv_bfloat16 g_wp_h  [256 * 256];
__device__ __nv_bfloat16 g_wp_l  [256 * 256];

// ------------------------------ helpers ------------------------------------
__device__ __forceinline__ uint32_t smem_u32(const void* p) {
    uint32_t a;
    asm("{ .reg .u64 t; cvta.to.shared.u64 t, %1; cvt.u32.u64 %0, t; }"
        : "=r"(a) : "l"(p));
    return a;
}

__device__ __forceinline__ void ldsm_x4(uint32_t* r, uint32_t addr) {
    asm volatile("ldmatrix.sync.aligned.m8n8.x4.shared.b16 {%0,%1,%2,%3}, [%4];"
        : "=r"(r[0]), "=r"(r[1]), "=r"(r[2]), "=r"(r[3]) : "r"(addr));
}

__device__ __forceinline__ void mma16816(float* c, const uint32_t* a,
                                         const uint32_t* b) {
    asm volatile(
        "mma.sync.aligned.m16n8k16.row.col.f32.bf16.bf16.f32 "
        "{%0,%1,%2,%3}, {%4,%5,%6,%7}, {%8,%9}, {%0,%1,%2,%3};"
        : "+f"(c[0]), "+f"(c[1]), "+f"(c[2]), "+f"(c[3])
        : "r"(a[0]), "r"(a[1]), "r"(a[2]), "r"(a[3]), "r"(b[0]), "r"(b[1]));
}

__device__ __forceinline__ void split2(float x, float y,
                                       uint32_t& h, uint32_t& l) {
    __nv_bfloat162 h2 = __floats2bfloat162_rn(x, y);
    float2 g = __bfloat1622float2(h2);
    __nv_bfloat162 l2 = __floats2bfloat162_rn(x - g.x, y - g.y);
    memcpy(&h, &h2, 4);
    memcpy(&l, &l2, 4);
}

// ---------------------------------------------------------------------------
// Weight split: fp32 -> (hi, lo) bf16 pairs.
// ---------------------------------------------------------------------------
__global__ void split_weights_kernel(const float* __restrict__ wqkv,
                                     const float* __restrict__ wp) {
    int i = blockIdx.x * blockDim.x + threadIdx.x;
    if (i < 768 * 256) {
        float f = wqkv[i];
        __nv_bfloat16 h = __float2bfloat16(f);
        g_wqkv_h[i] = h;
        g_wqkv_l[i] = __float2bfloat16(f - __bfloat162float(h));
    }
    if (i < 256 * 256) {
        float f = wp[i];
        __nv_bfloat16 h = __float2bfloat16(f);
        g_wp_h[i] = h;
        g_wp_l[i] = __float2bfloat16(f - __bfloat162float(h));
    }
}

// ---------------------------------------------------------------------------
// Tensor-core bf16x3 GEMM: C[m,n] = sum_k A[m,k]*W[n,k] + bias[n]
// Block tile 128x128, BK=32, double-buffered. 256 threads = 8 warps in a
// 4(m) x 2(n) grid; warp tile 32x64 -> 2 m16-tiles x 8 n8-tiles.
// SMEM rows padded to 40 bf16 (80B): 80 % 16 == 0 for ldmatrix, and the
// 20-words-per-row stride makes 8-row ldmatrix phases conflict-free.
// ---------------------------------------------------------------------------
#define KSTR     40                       // padded row length (bf16 elems)
#define ROWB     80                       // row bytes
#define OFF_AH   0
#define OFF_AL   10240
#define OFF_BH   20480
#define OFF_BL   30720
#define STAGE    40960
#define GEMM_SMEM (2 * STAGE)             // 81920 B

__global__ __launch_bounds__(256, 2) void mma_gemm_kernel(
    const float* __restrict__ A,
    const __nv_bfloat16* __restrict__ Wh, const __nv_bfloat16* __restrict__ Wl,
    const float* __restrict__ bias, float* __restrict__ C, int Ntot) {
    extern __shared__ char smem[];
    const uint32_t sb = smem_u32(smem);
    const int tid  = threadIdx.x;
    const int lane = tid & 31;
    const int w    = tid >> 5;
    const int wm   = (w & 3) * 32;
    const int wn   = (w >> 2) * 64;
    const long rowBase = (long)blockIdx.y * 128;
    const int  colBase = blockIdx.x * 128;

    // ldmatrix lane addressing
    const int a_r = lane & 15;                       // row within 16
    const int a_c = (lane >> 4) * 8;                 // col half (elems)
    const int b_n = (lane & 7) + ((lane >> 4) << 3); // n within 16
    const int b_k = ((lane >> 3) & 1) * 8;           // k half (elems)

    float acc[2][8][4];
#pragma unroll
    for (int mt = 0; mt < 2; mt++)
#pragma unroll
        for (int nt = 0; nt < 8; nt++)
#pragma unroll
            for (int j = 0; j < 4; j++) acc[mt][nt][j] = 0.0f;

    float4 af[4];
    uint4  b4[4];

#define LOAD_CHUNK(cc) do {                                                   \
    int k0 = (cc) * 32;                                                       \
    _Pragma("unroll")                                                         \
    for (int i = 0; i < 4; i++) {                                             \
        int idx = tid + i * 256;                                              \
        af[i] = __ldg((const float4*)(A + (rowBase + (idx >> 3)) * K_DIM      \
                                        + k0 + (idx & 7) * 4));               \
    }                                                                         \
    _Pragma("unroll")                                                         \
    for (int i = 0; i < 2; i++) {                                             \
        int idx = tid + i * 256;                                              \
        long g = (long)(colBase + (idx >> 2)) * K_DIM + k0 + (idx & 3) * 8;   \
        b4[i]     = __ldg((const uint4*)(Wh + g));                            \
        b4[i + 2] = __ldg((const uint4*)(Wl + g));                            \
    }                                                                         \
} while (0)

#define STORE_CHUNK(ss) do {                                                  \
    char* stp = smem + (ss) * STAGE;                                          \
    _Pragma("unroll")                                                         \
    for (int i = 0; i < 4; i++) {                                             \
        int idx = tid + i * 256;                                              \
        int row = idx >> 3, f4 = idx & 7;                                     \
        uint2 hh, ll;                                                         \
        split2(af[i].x, af[i].y, hh.x, ll.x);                                 \
        split2(af[i].z, af[i].w, hh.y, ll.y);                                 \
        uint32_t off = (uint32_t)(row * ROWB + f4 * 8);                       \
        *(uint2*)(stp + OFF_AH + off) = hh;                                   \
        *(uint2*)(stp + OFF_AL + off) = ll;                                   \
    }                                                                         \
    _Pragma("unroll")                                                         \
    for (int i = 0; i < 2; i++) {                                             \
        int idx = tid + i * 256;                                              \
        int n = idx >> 2, o = idx & 3;                                        \
        uint32_t off = (uint32_t)(n * ROWB + o * 16);                         \
        *(uint4*)(stp + OFF_BH + off) = b4[i];                                \
        *(uint4*)(stp + OFF_BL + off) = b4[i + 2];                            \
    }                                                                         \
} while (0)

    LOAD_CHUNK(0);
    STORE_CHUNK(0);
    __syncthreads();

    for (int c = 0; c < 8; c++) {
        const int s = c & 1;
        const bool more = (c + 1) < 8;
        if (more) LOAD_CHUNK(c + 1);

        const uint32_t stg = sb + s * STAGE;
#pragma unroll
        for (int ks = 0; ks < 2; ks++) {
            uint32_t ah[2][4], al[2][4];
#pragma unroll
            for (int mt = 0; mt < 2; mt++) {
                uint32_t off = (uint32_t)((wm + mt * 16 + a_r) * ROWB
                                          + (ks * 16 + a_c) * 2);
                ldsm_x4(ah[mt], stg + OFF_AH + off);
                ldsm_x4(al[mt], stg + OFF_AL + off);
            }
#pragma unroll
            for (int pr = 0; pr < 4; pr++) {
                uint32_t boff = (uint32_t)((wn + pr * 16 + b_n) * ROWB
                                           + (ks * 16 + b_k) * 2);
                uint32_t bh[4], bl[4];
                ldsm_x4(bh, stg + OFF_BH + boff);
                ldsm_x4(bl, stg + OFF_BL + boff);
#pragma unroll
                for (int mt = 0; mt < 2; mt++) {
                    mma16816(acc[mt][pr * 2],     ah[mt], bh);
                    mma16816(acc[mt][pr * 2 + 1], ah[mt], bh + 2);
                    mma16816(acc[mt][pr * 2],     al[mt], bh);
                    mma16816(acc[mt][pr * 2 + 1], al[mt], bh + 2);
                    mma16816(acc[mt][pr * 2],     ah[mt], bl);
                    mma16816(acc[mt][pr * 2 + 1], ah[mt], bl + 2);
                }
            }
        }

        if (more) STORE_CHUNK(s ^ 1);
        __syncthreads();
    }

    // Epilogue: acc -> C (+bias). Lane (t>>2) = row-in-8, (t&3)*2 = col pair.
    {
        const int r0 = wm + (lane >> 2);
        const int c0 = wn + (lane & 3) * 2;
#pragma unroll
        for (int mt = 0; mt < 2; mt++) {
#pragma unroll
            for (int nt = 0; nt < 8; nt++) {
                int col = colBase + c0 + nt * 8;
                float2 bv = __ldg((const float2*)(bias + col));
                long row = rowBase + r0 + mt * 16;
                float2 o0, o1;
                o0.x = acc[mt][nt][0] + bv.x;
                o0.y = acc[mt][nt][1] + bv.y;
                o1.x = acc[mt][nt][2] + bv.x;
                o1.y = acc[mt][nt][3] + bv.y;
                *(float2*)(C + row * Ntot + col)       = o0;
                *(float2*)(C + (row + 8) * Ntot + col) = o1;
            }
        }
    }
}

// ---------------------------------------------------------------------------
// Window attention (unchanged from passing baseline).
// ---------------------------------------------------------------------------
__global__ __launch_bounds__(256) void window_attn_kernel(
    const float* __restrict__ qkv, const float* __restrict__ bias_table,
    float* __restrict__ y) {
    const int head = blockIdx.x & 7;
    const int wi   = blockIdx.x >> 3;
    const int bimg = wi >> 10;
    const int widx = wi & 1023;
    const int wr   = widx >> 5;
    const int wc   = widx & 31;

    __shared__ float q_s[64][33];
    __shared__ float k_s[64][33];
    __shared__ float v_s[64][33];
    __shared__ float s_s[64][65];
    __shared__ float bias_s[225];

    const int tid = threadIdx.x;
    for (int i = tid; i < 225; i += 256) bias_s[i] = bias_table[i * 8 + head];

    const float scale = 0.17677669529663687f;

#pragma unroll
    for (int r = 0; r < 2; r++) {
        int q   = tid + r * 256;
        int tok = q >> 3;
        int dq  = (q & 7) * 4;
        long row = (long)bimg * 65536 + (long)(wr * 8 + (tok >> 3)) * 256 + wc * 8 + (tok & 7);
        const float* base = qkv + row * 768 + head * 32 + dq;
        float4 vq = *(const float4*)(base);
        float4 vk = *(const float4*)(base + 256);
        float4 vv = *(const float4*)(base + 512);
        q_s[tok][dq + 0] = vq.x * scale; q_s[tok][dq + 1] = vq.y * scale;
        q_s[tok][dq + 2] = vq.z * scale; q_s[tok][dq + 3] = vq.w * scale;
        k_s[tok][dq + 0] = vk.x; k_s[tok][dq + 1] = vk.y;
        k_s[tok][dq + 2] = vk.z; k_s[tok][dq + 3] = vk.w;
        v_s[tok][dq + 0] = vv.x; v_s[tok][dq + 1] = vv.y;
        v_s[tok][dq + 2] = vv.z; v_s[tok][dq + 3] = vv.w;
    }
    __syncthreads();

    {
        const int qg = tid >> 4;
        const int kg = tid & 15;
        float acc[4][4];
#pragma unroll
        for (int i = 0; i < 4; i++)
#pragma unroll
            for (int j = 0; j < 4; j++) acc[i][j] = 0.0f;

#pragma unroll 4
        for (int d = 0; d < 32; d++) {
            float qv[4], kv[4];
#pragma unroll
            for (int i = 0; i < 4; i++) qv[i] = q_s[qg * 4 + i][d];
#pragma unroll
            for (int j = 0; j < 4; j++) kv[j] = k_s[kg * 4 + j][d];
#pragma unroll
            for (int i = 0; i < 4; i++)
#pragma unroll
                for (int j = 0; j < 4; j++)
                    acc[i][j] = fmaf(qv[i], kv[j], acc[i][j]);
        }
#pragma unroll
        for (int i = 0; i < 4; i++)
#pragma unroll
            for (int j = 0; j < 4; j++) {
                int qi = qg * 4 + i, ki = kg * 4 + j;
                int idx = ((qi >> 3) - (ki >> 3) + 7) * 15 + ((qi & 7) - (ki & 7) + 7);
                s_s[qi][ki] = acc[i][j] + bias_s[idx];
            }
    }
    __syncthreads();

    if (tid < 64) {
        float m = -1e30f;
#pragma unroll 8
        for (int k = 0; k < 64; k++) m = fmaxf(m, s_s[tid][k]);
        float sum = 0.0f;
#pragma unroll 8
        for (int k = 0; k < 64; k++) {
            float e = __expf(s_s[tid][k] - m);
            s_s[tid][k] = e;
            sum += e;
        }
        float inv = 1.0f / sum;
#pragma unroll 8
        for (int k = 0; k < 64; k++) s_s[tid][k] *= inv;
    }
    __syncthreads();

    {
        const int d  = tid & 31;
        const int q0 = (tid >> 5) * 8;
        float out[8];
#pragma unroll
        for (int r = 0; r < 8; r++) out[r] = 0.0f;
#pragma unroll 4
        for (int ki = 0; ki < 64; ki++) {
            float vv = v_s[ki][d];
#pragma unroll
            for (int r = 0; r < 8; r++)
                out[r] = fmaf(s_s[q0 + r][ki], vv, out[r]);
        }
#pragma unroll
        for (int r = 0; r < 8; r++) {
            int tok = q0 + r;
            long row = (long)bimg * 65536 + (long)(wr * 8 + (tok >> 3)) * 256 + wc * 8 + (tok & 7);
            y[row * 256 + head * 32 + d] = out[r];
        }
    }
}

extern "C" void kernel_launch(void* const* d_in, const int* in_sizes, int n_in,
                              void* d_out, int out_size) {
    const float* x          = (const float*)d_in[0];
    const float* wqkv_w     = (const float*)d_in[3];
    const float* wqkv_b     = (const float*)d_in[4];
    const float* wp_w       = (const float*)d_in[5];
    const float* wp_b       = (const float*)d_in[6];
    const float* bias_table = (const float*)d_in[7];
    float* out = (float*)d_out;

    const int M = in_sizes[0] / K_DIM;         // 131072 rows

    float *qkv_ptr, *y_ptr;
    __nv_bfloat16 *wqh, *wql, *wph, *wpl;
    cudaGetSymbolAddress((void**)&qkv_ptr, g_qkv);
    cudaGetSymbolAddress((void**)&y_ptr,   g_y);
    cudaGetSymbolAddress((void**)&wqh, g_wqkv_h);
    cudaGetSymbolAddress((void**)&wql, g_wqkv_l);
    cudaGetSymbolAddress((void**)&wph, g_wp_h);
    cudaGetSymbolAddress((void**)&wpl, g_wp_l);

    cudaFuncSetAttribute(mma_gemm_kernel,
                         cudaFuncAttributeMaxDynamicSharedMemorySize, GEMM_SMEM);

    // 0) split weights into bf16 hi/lo
    split_weights_kernel<<<768, 256>>>(wqkv_w, wp_w);

    // 1) QKV projection: [M,256] @ [768,256]^T + b -> [M,768]
    {
        dim3 grid(6, M / 128);
        mma_gemm_kernel<<<grid, 256, GEMM_SMEM>>>(x, wqh, wql, wqkv_b, qkv_ptr, 768);
    }

    // 2) Window attention
    {
        int nblocks = (M / 65536) * 1024 * 8;
        window_attn_kernel<<<nblocks, 256>>>(qkv_ptr, bias_table, y_ptr);
    }

    // 3) Output projection: [M,256] @ [256,256]^T + b -> [M,256]
    {
        dim3 grid(2, M / 128);
        mma_gemm_kernel<<<grid, 256, GEMM_SMEM>>>(y_ptr, wph, wpl, wp_b, out, 256);
    }
}

// round 9
// speedup vs baseline: 2.0613x; 1.1274x over previous
#include <cuda_runtime.h>
#include <cuda_bf16.h>
#include <cstdint>
#include <cstring>

// ---------------------------------------------------------------------------
// SpatialWindowSelfAttention on GB300 (sm_103a), b=2, h=w=256, C=256,
// heads=8, head_dim=32, window 8x8 (ws=64).
//
//  1) split_weights_kernel : Wqkv/Wp fp32 -> (hi, lo) bf16
//  2) split_x_kernel       : x fp32 -> (hi, lo) bf16
//  3) mma_gemm_kernel (QKV): cp.async 3-stage + ldmatrix + mma.sync bf16x3
//  4) window_attn_kernel   : transposed-smem attention, writes y as bf16 h/l
//  5) mma_gemm_kernel (proj)
//
// bf16x3: A = Ah + Al, W = Wh + Wl; D += Ah*Wh + Ah*Wl + Al*Wh, fp32 accum.
// ---------------------------------------------------------------------------

#define K_DIM 256

// Scratch (b=2 fixed by the problem instance)
__device__ float g_qkv[131072ull * 768];            // 384 MiB
__device__ __nv_bfloat16 g_xh[131072ull * 256];     // 64 MiB
__device__ __nv_bfloat16 g_xl[131072ull * 256];
__device__ __nv_bfloat16 g_yh[131072ull * 256];
__device__ __nv_bfloat16 g_yl[131072ull * 256];
__device__ __nv_bfloat16 g_wqkv_h[768 * 256];
__device__ __nv_bfloat16 g_wqkv_l[768 * 256];
__device__ __nv_bfloat16 g_wp_h  [256 * 256];
__device__ __nv_bfloat16 g_wp_l  [256 * 256];

// ------------------------------ helpers ------------------------------------
__device__ __forceinline__ uint32_t smem_u32(const void* p) {
    uint32_t a;
    asm("{ .reg .u64 t; cvta.to.shared.u64 t, %1; cvt.u32.u64 %0, t; }"
        : "=r"(a) : "l"(p));
    return a;
}

__device__ __forceinline__ void ldsm_x4(uint32_t* r, uint32_t addr) {
    asm volatile("ldmatrix.sync.aligned.m8n8.x4.shared.b16 {%0,%1,%2,%3}, [%4];"
        : "=r"(r[0]), "=r"(r[1]), "=r"(r[2]), "=r"(r[3]) : "r"(addr));
}

__device__ __forceinline__ void mma16816(float* c, const uint32_t* a,
                                         const uint32_t* b) {
    asm volatile(
        "mma.sync.aligned.m16n8k16.row.col.f32.bf16.bf16.f32 "
        "{%0,%1,%2,%3}, {%4,%5,%6,%7}, {%8,%9}, {%0,%1,%2,%3};"
        : "+f"(c[0]), "+f"(c[1]), "+f"(c[2]), "+f"(c[3])
        : "r"(a[0]), "r"(a[1]), "r"(a[2]), "r"(a[3]), "r"(b[0]), "r"(b[1]));
}

__device__ __forceinline__ void cp_async16(uint32_t saddr, const void* g) {
    asm volatile("cp.async.cg.shared.global [%0], [%1], 16;"
        :: "r"(saddr), "l"(g));
}
#define CP_COMMIT() asm volatile("cp.async.commit_group;" ::: "memory")
#define CP_WAIT2()  asm volatile("cp.async.wait_group 2;"  ::: "memory")

__device__ __forceinline__ void split2(float x, float y,
                                       uint32_t& h, uint32_t& l) {
    __nv_bfloat162 h2 = __floats2bfloat162_rn(x, y);
    float2 g = __bfloat1622float2(h2);
    __nv_bfloat162 l2 = __floats2bfloat162_rn(x - g.x, y - g.y);
    memcpy(&h, &h2, 4);
    memcpy(&l, &l2, 4);
}

#define SW64(o) ((o) ^ (((o) >> 3) & 0x30))

// ---------------------------------------------------------------------------
// Splits
// ---------------------------------------------------------------------------
__global__ void split_weights_kernel(const float* __restrict__ wqkv,
                                     const float* __restrict__ wp) {
    int i = blockIdx.x * blockDim.x + threadIdx.x;
    if (i < 768 * 256) {
        float f = wqkv[i];
        __nv_bfloat16 h = __float2bfloat16(f);
        g_wqkv_h[i] = h;
        g_wqkv_l[i] = __float2bfloat16(f - __bfloat162float(h));
    }
    if (i < 256 * 256) {
        float f = wp[i];
        __nv_bfloat16 h = __float2bfloat16(f);
        g_wp_h[i] = h;
        g_wp_l[i] = __float2bfloat16(f - __bfloat162float(h));
    }
}

__global__ void split_x_kernel(const float* __restrict__ x) {
    long i = (long)(blockIdx.x * blockDim.x + threadIdx.x) * 4;
    float4 v = *(const float4*)(x + i);
    uint2 h, l;
    split2(v.x, v.y, h.x, l.x);
    split2(v.z, v.w, h.y, l.y);
    *(uint2*)(g_xh + i) = h;
    *(uint2*)(g_xl + i) = l;
}

// ---------------------------------------------------------------------------
// Tensor-core bf16x3 GEMM, cp.async 3-stage pipeline.
// Block tile 128x128, BK=32. 8 warps (4m x 2n), warp tile 32x64.
// SMEM: 4 tiles/stage (Ah,Al,Bh,Bl) of 128x32 bf16, 64B rows with SW64
// xor-swizzle (conflict-free ldmatrix). 3 stages x 32KB = 96KB -> 2 CTA/SM.
// ---------------------------------------------------------------------------
#define GOFF_AH 0
#define GOFF_AL 8192
#define GOFF_BH 16384
#define GOFF_BL 24576
#define GSTAGE  32768
#define GEMM_SMEM (3 * GSTAGE)            // 98304 B

__global__ __launch_bounds__(256, 2) void mma_gemm_kernel(
    const __nv_bfloat16* __restrict__ Ah, const __nv_bfloat16* __restrict__ Al,
    const __nv_bfloat16* __restrict__ Wh, const __nv_bfloat16* __restrict__ Wl,
    const float* __restrict__ bias, float* __restrict__ C, int Ntot) {
    extern __shared__ char smem[];
    const uint32_t sb = smem_u32(smem);
    const int tid  = threadIdx.x;
    const int lane = tid & 31;
    const int w    = tid >> 5;
    const int wm   = (w & 3) * 32;
    const int wn   = (w >> 2) * 64;
    const long rowBase = (long)blockIdx.y * 128;
    const int  colBase = blockIdx.x * 128;

    // ldmatrix lane addressing
    const int a_r = lane & 15;
    const int a_c = (lane >> 4) * 8;
    const int b_n = (lane & 7) + ((lane >> 4) << 3);
    const int b_k = ((lane >> 3) & 1) * 8;

    float acc[2][8][4];
#pragma unroll
    for (int mt = 0; mt < 2; mt++)
#pragma unroll
        for (int nt = 0; nt < 8; nt++)
#pragma unroll
            for (int j = 0; j < 4; j++) acc[mt][nt][j] = 0.0f;

#define GLOAD(cc, slot_) do {                                                 \
    int k0 = (cc) * 32;                                                       \
    uint32_t sbase = sb + (slot_) * GSTAGE;                                   \
    _Pragma("unroll")                                                         \
    for (int i = 0; i < 2; i++) {                                             \
        int li = tid + i * 256;                                               \
        int row = li >> 2, c4 = li & 3;                                       \
        uint32_t so = SW64((uint32_t)(row * 64 + c4 * 16));                   \
        long ga = (rowBase + row) * K_DIM + k0 + c4 * 8;                      \
        long gb = (long)(colBase + row) * K_DIM + k0 + c4 * 8;                \
        cp_async16(sbase + GOFF_AH + so, Ah + ga);                            \
        cp_async16(sbase + GOFF_AL + so, Al + ga);                            \
        cp_async16(sbase + GOFF_BH + so, Wh + gb);                            \
        cp_async16(sbase + GOFF_BL + so, Wl + gb);                            \
    }                                                                         \
} while (0)

    GLOAD(0, 0); CP_COMMIT();
    GLOAD(1, 1); CP_COMMIT();
    GLOAD(2, 2); CP_COMMIT();

    for (int c = 0; c < 8; c++) {
        CP_WAIT2();
        __syncthreads();
        const int slot = c % 3;
        const uint32_t stg = sb + slot * GSTAGE;

#pragma unroll
        for (int ks = 0; ks < 2; ks++) {
            uint32_t ah[2][4], al[2][4];
#pragma unroll
            for (int mt = 0; mt < 2; mt++) {
                uint32_t off = SW64((uint32_t)((wm + mt * 16 + a_r) * 64
                                               + (ks * 16 + a_c) * 2));
                ldsm_x4(ah[mt], stg + GOFF_AH + off);
                ldsm_x4(al[mt], stg + GOFF_AL + off);
            }
#pragma unroll
            for (int pr = 0; pr < 4; pr++) {
                uint32_t boff = SW64((uint32_t)((wn + pr * 16 + b_n) * 64
                                                + (ks * 16 + b_k) * 2));
                uint32_t bh[4], bl[4];
                ldsm_x4(bh, stg + GOFF_BH + boff);
                ldsm_x4(bl, stg + GOFF_BL + boff);
#pragma unroll
                for (int mt = 0; mt < 2; mt++) {
                    mma16816(acc[mt][pr * 2],     ah[mt], bh);
                    mma16816(acc[mt][pr * 2 + 1], ah[mt], bh + 2);
                    mma16816(acc[mt][pr * 2],     al[mt], bh);
                    mma16816(acc[mt][pr * 2 + 1], al[mt], bh + 2);
                    mma16816(acc[mt][pr * 2],     ah[mt], bl);
                    mma16816(acc[mt][pr * 2 + 1], ah[mt], bl + 2);
                }
            }
        }
        __syncthreads();
        if (c + 3 < 8) GLOAD(c + 3, slot);
        CP_COMMIT();
    }

    // Epilogue
    {
        const int r0 = wm + (lane >> 2);
        const int c0 = wn + (lane & 3) * 2;
#pragma unroll
        for (int mt = 0; mt < 2; mt++) {
#pragma unroll
            for (int nt = 0; nt < 8; nt++) {
                int col = colBase + c0 + nt * 8;
                float2 bv = __ldg((const float2*)(bias + col));
                long row = rowBase + r0 + mt * 16;
                float2 o0, o1;
                o0.x = acc[mt][nt][0] + bv.x;
                o0.y = acc[mt][nt][1] + bv.y;
                o1.x = acc[mt][nt][2] + bv.x;
                o1.y = acc[mt][nt][3] + bv.y;
                *(float2*)(C + row * Ntot + col)       = o0;
                *(float2*)(C + (row + 8) * Ntot + col) = o1;
            }
        }
    }
}

// ---------------------------------------------------------------------------
// Window attention v2: q/k/v stored d-major (transposed) in smem.
//   scores: per d, one LDS128 of 4 q-tokens + one LDS128 of 4 k-tokens.
//   softmax: 4 threads per row + shuffle reduce (all 256 threads active).
//   PV: s row LDS128 + broadcast vt LDS128.
// Writes y as bf16 (hi, lo) for the projection GEMM.
// ---------------------------------------------------------------------------
__global__ __launch_bounds__(256) void window_attn_kernel(
    const float* __restrict__ qkv, const float* __restrict__ bias_table,
    __nv_bfloat16* __restrict__ yh, __nv_bfloat16* __restrict__ yl) {
    const int head = blockIdx.x & 7;
    const int wi   = blockIdx.x >> 3;
    const int bimg = wi >> 10;
    const int widx = wi & 1023;
    const int wr   = widx >> 5;
    const int wc   = widx & 31;

    __shared__ float qt[32][68];        // [d][token]
    __shared__ float kt[32][68];
    __shared__ float vt[32][68];
    __shared__ float s_s[64][68];
    __shared__ float bias_s[225];

    const int tid = threadIdx.x;
    for (int i = tid; i < 225; i += 256) bias_s[i] = bias_table[i * 8 + head];

    const float scale = 0.17677669529663687f;

    // Load q,k,v (transposed into smem): 512 (tok, d-quad) units.
#pragma unroll
    for (int r = 0; r < 2; r++) {
        int q   = tid + r * 256;
        int tok = q >> 3;
        int dq  = (q & 7) * 4;
        long row = (long)bimg * 65536 + (long)(wr * 8 + (tok >> 3)) * 256 + wc * 8 + (tok & 7);
        const float* base = qkv + row * 768 + head * 32 + dq;
        float4 vq = *(const float4*)(base);
        float4 vk = *(const float4*)(base + 256);
        float4 vv = *(const float4*)(base + 512);
        qt[dq + 0][tok] = vq.x * scale; qt[dq + 1][tok] = vq.y * scale;
        qt[dq + 2][tok] = vq.z * scale; qt[dq + 3][tok] = vq.w * scale;
        kt[dq + 0][tok] = vk.x; kt[dq + 1][tok] = vk.y;
        kt[dq + 2][tok] = vk.z; kt[dq + 3][tok] = vk.w;
        vt[dq + 0][tok] = vv.x; vt[dq + 1][tok] = vv.y;
        vt[dq + 2][tok] = vv.z; vt[dq + 3][tok] = vv.w;
    }
    __syncthreads();

    // Scores: thread (qg, kg) computes 4x4 block; per d: 2 LDS128.
    {
        const int qg = tid >> 4;
        const int kg = tid & 15;
        float acc[4][4];
#pragma unroll
        for (int i = 0; i < 4; i++)
#pragma unroll
            for (int j = 0; j < 4; j++) acc[i][j] = 0.0f;

#pragma unroll 8
        for (int d = 0; d < 32; d++) {
            float4 qv = *(const float4*)&qt[d][qg * 4];
            float4 kv = *(const float4*)&kt[d][kg * 4];
            float qa[4] = {qv.x, qv.y, qv.z, qv.w};
            float ka[4] = {kv.x, kv.y, kv.z, kv.w};
#pragma unroll
            for (int i = 0; i < 4; i++)
#pragma unroll
                for (int j = 0; j < 4; j++)
                    acc[i][j] = fmaf(qa[i], ka[j], acc[i][j]);
        }
#pragma unroll
        for (int i = 0; i < 4; i++)
#pragma unroll
            for (int j = 0; j < 4; j++) {
                int qi = qg * 4 + i, ki = kg * 4 + j;
                int idx = ((qi >> 3) - (ki >> 3) + 7) * 15 + ((qi & 7) - (ki & 7) + 7);
                s_s[qi][ki] = acc[i][j] + bias_s[idx];
            }
    }
    __syncthreads();

    // Softmax: 4 threads per row, 16 cols each, shuffle reduce within quad.
    {
        const int row = tid >> 2;
        const int sub = tid & 3;
        float v[16];
#pragma unroll
        for (int q = 0; q < 4; q++) {
            float4 t = *(const float4*)&s_s[row][sub * 16 + q * 4];
            v[q * 4 + 0] = t.x; v[q * 4 + 1] = t.y;
            v[q * 4 + 2] = t.z; v[q * 4 + 3] = t.w;
        }
        float m = -1e30f;
#pragma unroll
        for (int k = 0; k < 16; k++) m = fmaxf(m, v[k]);
        m = fmaxf(m, __shfl_xor_sync(0xffffffffu, m, 1));
        m = fmaxf(m, __shfl_xor_sync(0xffffffffu, m, 2));
        float sum = 0.0f;
#pragma unroll
        for (int k = 0; k < 16; k++) {
            v[k] = __expf(v[k] - m);
            sum += v[k];
        }
        sum += __shfl_xor_sync(0xffffffffu, sum, 1);
        sum += __shfl_xor_sync(0xffffffffu, sum, 2);
        float inv = 1.0f / sum;
#pragma unroll
        for (int q = 0; q < 4; q++) {
            float4 t;
            t.x = v[q * 4 + 0] * inv; t.y = v[q * 4 + 1] * inv;
            t.z = v[q * 4 + 2] * inv; t.w = v[q * 4 + 3] * inv;
            *(float4*)&s_s[row][sub * 16 + q * 4] = t;
        }
    }
    __syncthreads();

    // PV: thread (r = tid&63, dg = tid>>6) computes row r, dims dg*8..+7.
    {
        const int r  = tid & 63;
        const int d0 = (tid >> 6) * 8;
        float out[8];
#pragma unroll
        for (int j = 0; j < 8; j++) out[j] = 0.0f;
#pragma unroll 4
        for (int ki = 0; ki < 64; ki += 4) {
            float4 sv = *(const float4*)&s_s[r][ki];
#pragma unroll
            for (int j = 0; j < 8; j++) {
                float4 vv = *(const float4*)&vt[d0 + j][ki];
                out[j] = fmaf(sv.x, vv.x, out[j]);
                out[j] = fmaf(sv.y, vv.y, out[j]);
                out[j] = fmaf(sv.z, vv.z, out[j]);
                out[j] = fmaf(sv.w, vv.w, out[j]);
            }
        }
        long row = (long)bimg * 65536 + (long)(wr * 8 + (r >> 3)) * 256 + wc * 8 + (r & 7);
        long off = row * 256 + head * 32 + d0;
        uint4 hq, lq;
        split2(out[0], out[1], hq.x, lq.x);
        split2(out[2], out[3], hq.y, lq.y);
        split2(out[4], out[5], hq.z, lq.z);
        split2(out[6], out[7], hq.w, lq.w);
        *(uint4*)(yh + off) = hq;
        *(uint4*)(yl + off) = lq;
    }
}

extern "C" void kernel_launch(void* const* d_in, const int* in_sizes, int n_in,
                              void* d_out, int out_size) {
    const float* x          = (const float*)d_in[0];
    const float* wqkv_w     = (const float*)d_in[3];
    const float* wqkv_b     = (const float*)d_in[4];
    const float* wp_w       = (const float*)d_in[5];
    const float* wp_b       = (const float*)d_in[6];
    const float* bias_table = (const float*)d_in[7];
    float* out = (float*)d_out;

    const int M = in_sizes[0] / K_DIM;         // 131072 rows

    float* qkv_ptr;
    __nv_bfloat16 *xh, *xl, *yh, *yl, *wqh, *wql, *wph, *wpl;
    cudaGetSymbolAddress((void**)&qkv_ptr, g_qkv);
    cudaGetSymbolAddress((void**)&xh, g_xh);
    cudaGetSymbolAddress((void**)&xl, g_xl);
    cudaGetSymbolAddress((void**)&yh, g_yh);
    cudaGetSymbolAddress((void**)&yl, g_yl);
    cudaGetSymbolAddress((void**)&wqh, g_wqkv_h);
    cudaGetSymbolAddress((void**)&wql, g_wqkv_l);
    cudaGetSymbolAddress((void**)&wph, g_wp_h);
    cudaGetSymbolAddress((void**)&wpl, g_wp_l);

    cudaFuncSetAttribute(mma_gemm_kernel,
                         cudaFuncAttributeMaxDynamicSharedMemorySize, GEMM_SMEM);

    // 0) splits
    split_weights_kernel<<<768, 256>>>(wqkv_w, wp_w);
    split_x_kernel<<<(M * K_DIM) / (4 * 256), 256>>>(x);

    // 1) QKV projection: [M,256] @ [768,256]^T + b -> [M,768]
    {
        dim3 grid(6, M / 128);
        mma_gemm_kernel<<<grid, 256, GEMM_SMEM>>>(xh, xl, wqh, wql, wqkv_b,
                                                  qkv_ptr, 768);
    }

    // 2) Window attention (writes y split into bf16 hi/lo)
    {
        int nblocks = (M / 65536) * 1024 * 8;
        window_attn_kernel<<<nblocks, 256>>>(qkv_ptr, bias_table, yh, yl);
    }

    // 3) Output projection: [M,256] @ [256,256]^T + b -> [M,256]
    {
        dim3 grid(2, M / 128);
        mma_gemm_kernel<<<grid, 256, GEMM_SMEM>>>(yh, yl, wph, wpl, wp_b,
                                                  out, 256);
    }
}

// round 11
// speedup vs baseline: 2.6858x; 1.3030x over previous
#include <cuda_runtime.h>
#include <cuda_bf16.h>
#include <cuda_fp16.h>
#include <cstdint>
#include <cstring>

// ---------------------------------------------------------------------------
// SpatialWindowSelfAttention on GB300 (sm_103a), b=2, h=w=256, C=256,
// heads=8, head_dim=32, window 8x8 (ws=64).
//
//  1) split_weights_kernel : Wqkv/Wp fp32 -> (hi, lo) bf16
//  2) split_x_kernel       : x fp32 -> (hi, lo) bf16
//  3) mma_gemm_kernel (QKV): cp.async 3-stage + ldmatrix + mma.sync bf16x3
//  4) window_attn_kernel   : tensor-core attention (fp16x2 split QK and PV,
//                            FA-style P reuse from C fragments)
//  5) mma_gemm_kernel (proj)
// ---------------------------------------------------------------------------

#define K_DIM 256

// Scratch (b=2 fixed by the problem instance)
__device__ float g_qkv[131072ull * 768];            // 384 MiB
__device__ __nv_bfloat16 g_xh[131072ull * 256];     // 64 MiB
__device__ __nv_bfloat16 g_xl[131072ull * 256];
__device__ __nv_bfloat16 g_yh[131072ull * 256];
__device__ __nv_bfloat16 g_yl[131072ull * 256];
__device__ __nv_bfloat16 g_wqkv_h[768 * 256];
__device__ __nv_bfloat16 g_wqkv_l[768 * 256];
__device__ __nv_bfloat16 g_wp_h  [256 * 256];
__device__ __nv_bfloat16 g_wp_l  [256 * 256];

// ------------------------------ helpers ------------------------------------
__device__ __forceinline__ uint32_t smem_u32(const void* p) {
    uint32_t a;
    asm("{ .reg .u64 t; cvta.to.shared.u64 t, %1; cvt.u32.u64 %0, t; }"
        : "=r"(a) : "l"(p));
    return a;
}

__device__ __forceinline__ void ldsm_x4(uint32_t* r, uint32_t addr) {
    asm volatile("ldmatrix.sync.aligned.m8n8.x4.shared.b16 {%0,%1,%2,%3}, [%4];"
        : "=r"(r[0]), "=r"(r[1]), "=r"(r[2]), "=r"(r[3]) : "r"(addr));
}

__device__ __forceinline__ void mma16816(float* c, const uint32_t* a,
                                         const uint32_t* b) {
    asm volatile(
        "mma.sync.aligned.m16n8k16.row.col.f32.bf16.bf16.f32 "
        "{%0,%1,%2,%3}, {%4,%5,%6,%7}, {%8,%9}, {%0,%1,%2,%3};"
        : "+f"(c[0]), "+f"(c[1]), "+f"(c[2]), "+f"(c[3])
        : "r"(a[0]), "r"(a[1]), "r"(a[2]), "r"(a[3]), "r"(b[0]), "r"(b[1]));
}

__device__ __forceinline__ void mma16816h(float* c, const uint32_t* a,
                                          const uint32_t* b) {
    asm volatile(
        "mma.sync.aligned.m16n8k16.row.col.f32.f16.f16.f32 "
        "{%0,%1,%2,%3}, {%4,%5,%6,%7}, {%8,%9}, {%0,%1,%2,%3};"
        : "+f"(c[0]), "+f"(c[1]), "+f"(c[2]), "+f"(c[3])
        : "r"(a[0]), "r"(a[1]), "r"(a[2]), "r"(a[3]), "r"(b[0]), "r"(b[1]));
}

__device__ __forceinline__ void cp_async16(uint32_t saddr, const void* g) {
    asm volatile("cp.async.cg.shared.global [%0], [%1], 16;"
        :: "r"(saddr), "l"(g));
}
#define CP_COMMIT() asm volatile("cp.async.commit_group;" ::: "memory")
#define CP_WAIT2()  asm volatile("cp.async.wait_group 2;"  ::: "memory")

__device__ __forceinline__ void split2(float x, float y,
                                       uint32_t& h, uint32_t& l) {
    __nv_bfloat162 h2 = __floats2bfloat162_rn(x, y);
    float2 g = __bfloat1622float2(h2);
    __nv_bfloat162 l2 = __floats2bfloat162_rn(x - g.x, y - g.y);
    memcpy(&h, &h2, 4);
    memcpy(&l, &l2, 4);
}

__device__ __forceinline__ void split2h(float x, float y,
                                        uint32_t& h, uint32_t& l) {
    __half2 h2 = __floats2half2_rn(x, y);
    float2 g = __half22float2(h2);
    __half2 l2 = __floats2half2_rn(x - g.x, y - g.y);
    memcpy(&h, &h2, 4);
    memcpy(&l, &l2, 4);
}

#define SW64(o) ((o) ^ (((o) >> 3) & 0x30))

// ---------------------------------------------------------------------------
// Splits
// ---------------------------------------------------------------------------
__global__ void split_weights_kernel(const float* __restrict__ wqkv,
                                     const float* __restrict__ wp) {
    int i = blockIdx.x * blockDim.x + threadIdx.x;
    if (i < 768 * 256) {
        float f = wqkv[i];
        __nv_bfloat16 h = __float2bfloat16(f);
        g_wqkv_h[i] = h;
        g_wqkv_l[i] = __float2bfloat16(f - __bfloat162float(h));
    }
    if (i < 256 * 256) {
        float f = wp[i];
        __nv_bfloat16 h = __float2bfloat16(f);
        g_wp_h[i] = h;
        g_wp_l[i] = __float2bfloat16(f - __bfloat162float(h));
    }
}

__global__ void split_x_kernel(const float* __restrict__ x) {
    long i = (long)(blockIdx.x * blockDim.x + threadIdx.x) * 4;
    float4 v = *(const float4*)(x + i);
    uint2 h, l;
    split2(v.x, v.y, h.x, l.x);
    split2(v.z, v.w, h.y, l.y);
    *(uint2*)(g_xh + i) = h;
    *(uint2*)(g_xl + i) = l;
}

// ---------------------------------------------------------------------------
// Tensor-core bf16x3 GEMM, cp.async 3-stage pipeline (unchanged from R8).
// ---------------------------------------------------------------------------
#define GOFF_AH 0
#define GOFF_AL 8192
#define GOFF_BH 16384
#define GOFF_BL 24576
#define GSTAGE  32768
#define GEMM_SMEM (3 * GSTAGE)            // 98304 B

__global__ __launch_bounds__(256, 2) void mma_gemm_kernel(
    const __nv_bfloat16* __restrict__ Ah, const __nv_bfloat16* __restrict__ Al,
    const __nv_bfloat16* __restrict__ Wh, const __nv_bfloat16* __restrict__ Wl,
    const float* __restrict__ bias, float* __restrict__ C, int Ntot) {
    extern __shared__ char smem[];
    const uint32_t sb = smem_u32(smem);
    const int tid  = threadIdx.x;
    const int lane = tid & 31;
    const int w    = tid >> 5;
    const int wm   = (w & 3) * 32;
    const int wn   = (w >> 2) * 64;
    const long rowBase = (long)blockIdx.y * 128;
    const int  colBase = blockIdx.x * 128;

    const int a_r = lane & 15;
    const int a_c = (lane >> 4) * 8;
    const int b_n = (lane & 7) + ((lane >> 4) << 3);
    const int b_k = ((lane >> 3) & 1) * 8;

    float acc[2][8][4];
#pragma unroll
    for (int mt = 0; mt < 2; mt++)
#pragma unroll
        for (int nt = 0; nt < 8; nt++)
#pragma unroll
            for (int j = 0; j < 4; j++) acc[mt][nt][j] = 0.0f;

#define GLOAD(cc, slot_) do {                                                 \
    int k0 = (cc) * 32;                                                       \
    uint32_t sbase = sb + (slot_) * GSTAGE;                                   \
    _Pragma("unroll")                                                         \
    for (int i = 0; i < 2; i++) {                                             \
        int li = tid + i * 256;                                               \
        int row = li >> 2, c4 = li & 3;                                       \
        uint32_t so = SW64((uint32_t)(row * 64 + c4 * 16));                   \
        long ga = (rowBase + row) * K_DIM + k0 + c4 * 8;                      \
        long gb = (long)(colBase + row) * K_DIM + k0 + c4 * 8;                \
        cp_async16(sbase + GOFF_AH + so, Ah + ga);                            \
        cp_async16(sbase + GOFF_AL + so, Al + ga);                            \
        cp_async16(sbase + GOFF_BH + so, Wh + gb);                            \
        cp_async16(sbase + GOFF_BL + so, Wl + gb);                            \
    }                                                                         \
} while (0)

    GLOAD(0, 0); CP_COMMIT();
    GLOAD(1, 1); CP_COMMIT();
    GLOAD(2, 2); CP_COMMIT();

    for (int c = 0; c < 8; c++) {
        CP_WAIT2();
        __syncthreads();
        const int slot = c % 3;
        const uint32_t stg = sb + slot * GSTAGE;

#pragma unroll
        for (int ks = 0; ks < 2; ks++) {
            uint32_t ah[2][4], al[2][4];
#pragma unroll
            for (int mt = 0; mt < 2; mt++) {
                uint32_t off = SW64((uint32_t)((wm + mt * 16 + a_r) * 64
                                               + (ks * 16 + a_c) * 2));
                ldsm_x4(ah[mt], stg + GOFF_AH + off);
                ldsm_x4(al[mt], stg + GOFF_AL + off);
            }
#pragma unroll
            for (int pr = 0; pr < 4; pr++) {
                uint32_t boff = SW64((uint32_t)((wn + pr * 16 + b_n) * 64
                                                + (ks * 16 + b_k) * 2));
                uint32_t bh[4], bl[4];
                ldsm_x4(bh, stg + GOFF_BH + boff);
                ldsm_x4(bl, stg + GOFF_BL + boff);
#pragma unroll
                for (int mt = 0; mt < 2; mt++) {
                    mma16816(acc[mt][pr * 2],     ah[mt], bh);
                    mma16816(acc[mt][pr * 2 + 1], ah[mt], bh + 2);
                    mma16816(acc[mt][pr * 2],     al[mt], bh);
                    mma16816(acc[mt][pr * 2 + 1], al[mt], bh + 2);
                    mma16816(acc[mt][pr * 2],     ah[mt], bl);
                    mma16816(acc[mt][pr * 2 + 1], ah[mt], bl + 2);
                }
            }
        }
        __syncthreads();
        if (c + 3 < 8) GLOAD(c + 3, slot);
        CP_COMMIT();
    }

    {
        const int r0 = wm + (lane >> 2);
        const int c0 = wn + (lane & 3) * 2;
#pragma unroll
        for (int mt = 0; mt < 2; mt++) {
#pragma unroll
            for (int nt = 0; nt < 8; nt++) {
                int col = colBase + c0 + nt * 8;
                float2 bv = __ldg((const float2*)(bias + col));
                long row = rowBase + r0 + mt * 16;
                float2 o0, o1;
                o0.x = acc[mt][nt][0] + bv.x;
                o0.y = acc[mt][nt][1] + bv.y;
                o1.x = acc[mt][nt][2] + bv.x;
                o1.y = acc[mt][nt][3] + bv.y;
                *(float2*)(C + row * Ntot + col)       = o0;
                *(float2*)(C + (row + 8) * Ntot + col) = o1;
            }
        }
    }
}

// ---------------------------------------------------------------------------
// Tensor-core window attention. One block = one (window, head), 128 threads.
// Warp w computes q-rows [w*16, w*16+16) of the 64x64 score matrix.
//   S = Qh*Kh + Qh*Kl + Ql*Kh   (fp16 hi/lo split, fp32 accum)
//   softmax on C fragments (shuffle over 4-lane row groups)
//   P fp16 hi/lo built in-register from C frags (FA layout trick)
//   Y = Ph*Vh + Ph*Vl + Pl*Vh
// Q/K smem: [tok][d] stride 40 fp16 (conflict-free ldmatrix).
// V smem: transposed [d][tok] stride 72 fp16 (conflict-free ldmatrix).
// ---------------------------------------------------------------------------
#define QK_STR 40
#define VT_STR 72

__global__ __launch_bounds__(128) void window_attn_kernel(
    const float* __restrict__ qkv, const float* __restrict__ bias_table,
    __nv_bfloat16* __restrict__ yh, __nv_bfloat16* __restrict__ yl) {
    const int head = blockIdx.x & 7;
    const int wi   = blockIdx.x >> 3;
    const int bimg = wi >> 10;
    const int widx = wi & 1023;
    const int wr   = widx >> 5;
    const int wc   = widx & 31;

    __shared__ __half qh_s[64 * QK_STR];
    __shared__ __half ql_s[64 * QK_STR];
    __shared__ __half kh_s[64 * QK_STR];
    __shared__ __half kl_s[64 * QK_STR];
    __shared__ __half vh_s[32 * VT_STR];
    __shared__ __half vl_s[32 * VT_STR];
    __shared__ float  bias_s[225];

    const int tid  = threadIdx.x;
    const int lane = tid & 31;
    const int w    = tid >> 5;

    for (int i = tid; i < 225; i += 128) bias_s[i] = bias_table[i * 8 + head];

    const float scale = 0.17677669529663687f;   // 1/sqrt(32)

    // Load q,k,v: 512 (tok, d-quad) units, 4 per thread.
#pragma unroll
    for (int r = 0; r < 4; r++) {
        int q   = tid + r * 128;
        int tok = q >> 3;
        int dq  = (q & 7) * 4;
        long row = (long)bimg * 65536 + (long)(wr * 8 + (tok >> 3)) * 256 + wc * 8 + (tok & 7);
        const float* base = qkv + row * 768 + head * 32 + dq;
        float4 vq = *(const float4*)(base);
        float4 vk = *(const float4*)(base + 256);
        float4 vv = *(const float4*)(base + 512);
        uint32_t h0, l0, h1, l1;
        // Q (scaled)
        split2h(vq.x * scale, vq.y * scale, h0, l0);
        split2h(vq.z * scale, vq.w * scale, h1, l1);
        *(uint32_t*)&qh_s[tok * QK_STR + dq]     = h0;
        *(uint32_t*)&qh_s[tok * QK_STR + dq + 2] = h1;
        *(uint32_t*)&ql_s[tok * QK_STR + dq]     = l0;
        *(uint32_t*)&ql_s[tok * QK_STR + dq + 2] = l1;
        // K
        split2h(vk.x, vk.y, h0, l0);
        split2h(vk.z, vk.w, h1, l1);
        *(uint32_t*)&kh_s[tok * QK_STR + dq]     = h0;
        *(uint32_t*)&kh_s[tok * QK_STR + dq + 2] = h1;
        *(uint32_t*)&kl_s[tok * QK_STR + dq]     = l0;
        *(uint32_t*)&kl_s[tok * QK_STR + dq + 2] = l1;
        // V transposed [d][tok]
        float vf[4] = {vv.x, vv.y, vv.z, vv.w};
#pragma unroll
        for (int j = 0; j < 4; j++) {
            __half hv = __float2half_rn(vf[j]);
            __half lv = __float2half_rn(vf[j] - __half2float(hv));
            vh_s[(dq + j) * VT_STR + tok] = hv;
            vl_s[(dq + j) * VT_STR + tok] = lv;
        }
    }
    __syncthreads();

    // ldmatrix lane addressing (same scheme as the proven GEMM kernel)
    const int a_r = lane & 15;
    const int a_c = (lane >> 4) * 8;
    const int b_n = (lane & 7) + ((lane >> 4) << 3);
    const int b_k = ((lane >> 3) & 1) * 8;

    const uint32_t qh_b = smem_u32(qh_s), ql_b = smem_u32(ql_s);
    const uint32_t kh_b = smem_u32(kh_s), kl_b = smem_u32(kl_s);
    const uint32_t vh_b = smem_u32(vh_s), vl_b = smem_u32(vl_s);

    const int wrow = w * 16;

    // ---- scores: S (16 x 64) in 8 n8-tiles of C fragments ----
    uint32_t qhf[2][4], qlf[2][4];
#pragma unroll
    for (int ks = 0; ks < 2; ks++) {
        uint32_t off = (uint32_t)(((wrow + a_r) * QK_STR + ks * 16 + a_c) * 2);
        ldsm_x4(qhf[ks], qh_b + off);
        ldsm_x4(qlf[ks], ql_b + off);
    }

    float sacc[8][4];
#pragma unroll
    for (int nt = 0; nt < 8; nt++)
#pragma unroll
        for (int j = 0; j < 4; j++) sacc[nt][j] = 0.0f;

#pragma unroll
    for (int nt2 = 0; nt2 < 4; nt2++) {      // 16 key-tokens per iter
#pragma unroll
        for (int ks = 0; ks < 2; ks++) {
            uint32_t off = (uint32_t)(((nt2 * 16 + b_n) * QK_STR + ks * 16 + b_k) * 2);
            uint32_t khf[4], klf[4];
            ldsm_x4(khf, kh_b + off);
            ldsm_x4(klf, kl_b + off);
            mma16816h(sacc[nt2 * 2],     qhf[ks], khf);
            mma16816h(sacc[nt2 * 2 + 1], qhf[ks], khf + 2);
            mma16816h(sacc[nt2 * 2],     qhf[ks], klf);
            mma16816h(sacc[nt2 * 2 + 1], qhf[ks], klf + 2);
            mma16816h(sacc[nt2 * 2],     qlf[ks], khf);
            mma16816h(sacc[nt2 * 2 + 1], qlf[ks], khf + 2);
        }
    }

    // ---- bias + softmax on fragments ----
    const int fr  = lane >> 2;           // row within 16 (and +8)
    const int fc  = (lane & 3) * 2;      // col pair within n8 tile
    const int qi0 = wrow + fr;
    const int qi1 = qi0 + 8;

    float m0 = -1e30f, m1 = -1e30f;
#pragma unroll
    for (int nt = 0; nt < 8; nt++) {
        int ki = nt * 8 + fc;
        int q0r = qi0 >> 3, q0c = qi0 & 7, q1r = qi1 >> 3, q1c = qi1 & 7;
        int k0r = ki >> 3,  k0c = ki & 7,  k1r = (ki + 1) >> 3, k1c = (ki + 1) & 7;
        sacc[nt][0] += bias_s[(q0r - k0r + 7) * 15 + (q0c - k0c + 7)];
        sacc[nt][1] += bias_s[(q0r - k1r + 7) * 15 + (q0c - k1c + 7)];
        sacc[nt][2] += bias_s[(q1r - k0r + 7) * 15 + (q1c - k0c + 7)];
        sacc[nt][3] += bias_s[(q1r - k1r + 7) * 15 + (q1c - k1c + 7)];
        m0 = fmaxf(m0, fmaxf(sacc[nt][0], sacc[nt][1]));
        m1 = fmaxf(m1, fmaxf(sacc[nt][2], sacc[nt][3]));
    }
    m0 = fmaxf(m0, __shfl_xor_sync(0xffffffffu, m0, 1));
    m0 = fmaxf(m0, __shfl_xor_sync(0xffffffffu, m0, 2));
    m1 = fmaxf(m1, __shfl_xor_sync(0xffffffffu, m1, 1));
    m1 = fmaxf(m1, __shfl_xor_sync(0xffffffffu, m1, 2));

    float s0 = 0.0f, s1 = 0.0f;
#pragma unroll
    for (int nt = 0; nt < 8; nt++) {
        sacc[nt][0] = __expf(sacc[nt][0] - m0);
        sacc[nt][1] = __expf(sacc[nt][1] - m0);
        sacc[nt][2] = __expf(sacc[nt][2] - m1);
        sacc[nt][3] = __expf(sacc[nt][3] - m1);
        s0 += sacc[nt][0] + sacc[nt][1];
        s1 += sacc[nt][2] + sacc[nt][3];
    }
    s0 += __shfl_xor_sync(0xffffffffu, s0, 1);
    s0 += __shfl_xor_sync(0xffffffffu, s0, 2);
    s1 += __shfl_xor_sync(0xffffffffu, s1, 1);
    s1 += __shfl_xor_sync(0xffffffffu, s1, 2);
    const float inv0 = 1.0f / s0;
    const float inv1 = 1.0f / s1;

    // ---- P fragments (fp16 hi/lo) from C fragments: FA layout trick ----
    uint32_t ph[4][4], pl[4][4];
#pragma unroll
    for (int kk = 0; kk < 4; kk++) {
        const int t0 = kk * 2, t1 = kk * 2 + 1;
        split2h(sacc[t0][0] * inv0, sacc[t0][1] * inv0, ph[kk][0], pl[kk][0]);
        split2h(sacc[t0][2] * inv1, sacc[t0][3] * inv1, ph[kk][1], pl[kk][1]);
        split2h(sacc[t1][0] * inv0, sacc[t1][1] * inv0, ph[kk][2], pl[kk][2]);
        split2h(sacc[t1][2] * inv1, sacc[t1][3] * inv1, ph[kk][3], pl[kk][3]);
    }

    // ---- PV: Y (16 x 32) in 4 n8-tiles ----
    float oacc[4][4];
#pragma unroll
    for (int nt = 0; nt < 4; nt++)
#pragma unroll
        for (int j = 0; j < 4; j++) oacc[nt][j] = 0.0f;

#pragma unroll
    for (int kk = 0; kk < 4; kk++) {         // 16 tokens per kstep
#pragma unroll
        for (int nt2 = 0; nt2 < 2; nt2++) {  // 16 dims per iter
            uint32_t off = (uint32_t)(((nt2 * 16 + b_n) * VT_STR + kk * 16 + b_k) * 2);
            uint32_t vhf[4], vlf[4];
            ldsm_x4(vhf, vh_b + off);
            ldsm_x4(vlf, vl_b + off);
            mma16816h(oacc[nt2 * 2],     ph[kk], vhf);
            mma16816h(oacc[nt2 * 2 + 1], ph[kk], vhf + 2);
            mma16816h(oacc[nt2 * 2],     ph[kk], vlf);
            mma16816h(oacc[nt2 * 2 + 1], ph[kk], vlf + 2);
            mma16816h(oacc[nt2 * 2],     pl[kk], vhf);
            mma16816h(oacc[nt2 * 2 + 1], pl[kk], vhf + 2);
        }
    }

    // ---- write y as bf16 hi/lo ----
    {
        long row0 = (long)bimg * 65536 + (long)(wr * 8 + (qi0 >> 3)) * 256 + wc * 8 + (qi0 & 7);
        long row1 = (long)bimg * 65536 + (long)(wr * 8 + (qi1 >> 3)) * 256 + wc * 8 + (qi1 & 7);
#pragma unroll
        for (int nt = 0; nt < 4; nt++) {
            int d = nt * 8 + fc;
            long off0 = row0 * 256 + head * 32 + d;
            long off1 = row1 * 256 + head * 32 + d;
            uint32_t hq, lq;
            split2(oacc[nt][0], oacc[nt][1], hq, lq);
            *(uint32_t*)(yh + off0) = hq;
            *(uint32_t*)(yl + off0) = lq;
            split2(oacc[nt][2], oacc[nt][3], hq, lq);
            *(uint32_t*)(yh + off1) = hq;
            *(uint32_t*)(yl + off1) = lq;
        }
    }
}

extern "C" void kernel_launch(void* const* d_in, const int* in_sizes, int n_in,
                              void* d_out, int out_size) {
    const float* x          = (const float*)d_in[0];
    const float* wqkv_w     = (const float*)d_in[3];
    const float* wqkv_b     = (const float*)d_in[4];
    const float* wp_w       = (const float*)d_in[5];
    const float* wp_b       = (const float*)d_in[6];
    const float* bias_table = (const float*)d_in[7];
    float* out = (float*)d_out;

    const int M = in_sizes[0] / K_DIM;         // 131072 rows

    float* qkv_ptr;
    __nv_bfloat16 *xh, *xl, *yh, *yl, *wqh, *wql, *wph, *wpl;
    cudaGetSymbolAddress((void**)&qkv_ptr, g_qkv);
    cudaGetSymbolAddress((void**)&xh, g_xh);
    cudaGetSymbolAddress((void**)&xl, g_xl);
    cudaGetSymbolAddress((void**)&yh, g_yh);
    cudaGetSymbolAddress((void**)&yl, g_yl);
    cudaGetSymbolAddress((void**)&wqh, g_wqkv_h);
    cudaGetSymbolAddress((void**)&wql, g_wqkv_l);
    cudaGetSymbolAddress((void**)&wph, g_wp_h);
    cudaGetSymbolAddress((void**)&wpl, g_wp_l);

    cudaFuncSetAttribute(mma_gemm_kernel,
                         cudaFuncAttributeMaxDynamicSharedMemorySize, GEMM_SMEM);

    // 0) splits
    split_weights_kernel<<<768, 256>>>(wqkv_w, wp_w);
    split_x_kernel<<<(M * K_DIM) / (4 * 256), 256>>>(x);

    // 1) QKV projection: [M,256] @ [768,256]^T + b -> [M,768]
    {
        dim3 grid(6, M / 128);
        mma_gemm_kernel<<<grid, 256, GEMM_SMEM>>>(xh, xl, wqh, wql, wqkv_b,
                                                  qkv_ptr, 768);
    }

    // 2) Window attention (tensor cores; writes y split into bf16 hi/lo)
    {
        int nblocks = (M / 65536) * 1024 * 8;
        window_attn_kernel<<<nblocks, 128>>>(qkv_ptr, bias_table, yh, yl);
    }

    // 3) Output projection: [M,256] @ [256,256]^T + b -> [M,256]
    {
        dim3 grid(2, M / 128);
        mma_gemm_kernel<<<grid, 256, GEMM_SMEM>>>(yh, yl, wph, wpl, wp_b,
                                                  out, 256);
    }
}

// round 13
// speedup vs baseline: 3.3858x; 1.2606x over previous
#include <cuda_runtime.h>
#include <cuda_bf16.h>
#include <cuda_fp16.h>
#include <cstdint>
#include <cstring>

// ---------------------------------------------------------------------------
// SpatialWindowSelfAttention on GB300 (sm_103a), b=2, h=w=256, C=256,
// heads=8, head_dim=32, window 8x8 (ws=64).
//
//  1) split_weights_kernel : Wqkv/Wp fp32 -> (hi, lo) bf16
//  2) split_x_kernel       : x fp32 -> (hi, lo) bf16
//  3) tc_gemm_kernel (QKV) : tcgen05 SS bf16x3 GEMM (128x256 tile, K=64
//                            chunks, cp.async + SW128, mbarrier-paced)
//  4) window_attn_kernel   : tensor-core attention (mma.sync fp16x2)
//  5) tc_gemm_kernel (proj)
//
// tcgen05 is feature-gated: the compute_103 (non-'a') ptxas pass rejects
// tcgen05 (R5 post-mortem), so that pass compiles a stub. On GB300 the
// exact sm_103a cubin is selected, which contains the real body.
// ---------------------------------------------------------------------------

#define K_DIM 256

// Scratch (b=2 fixed by the problem instance)
__device__ float g_qkv[131072ull * 768];            // 384 MiB
__device__ __nv_bfloat16 g_xh[131072ull * 256];     // 64 MiB
__device__ __nv_bfloat16 g_xl[131072ull * 256];
__device__ __nv_bfloat16 g_yh[131072ull * 256];
__device__ __nv_bfloat16 g_yl[131072ull * 256];
__device__ __nv_bfloat16 g_wqkv_h[768 * 256];
__device__ __nv_bfloat16 g_wqkv_l[768 * 256];
__device__ __nv_bfloat16 g_wp_h  [256 * 256];
__device__ __nv_bfloat16 g_wp_l  [256 * 256];

// ------------------------------ helpers ------------------------------------
__device__ __forceinline__ uint32_t smem_u32(const void* p) {
    uint32_t a;
    asm("{ .reg .u64 t; cvta.to.shared.u64 t, %1; cvt.u32.u64 %0, t; }"
        : "=r"(a) : "l"(p));
    return a;
}

__device__ __forceinline__ void ldsm_x4(uint32_t* r, uint32_t addr) {
    asm volatile("ldmatrix.sync.aligned.m8n8.x4.shared.b16 {%0,%1,%2,%3}, [%4];"
        : "=r"(r[0]), "=r"(r[1]), "=r"(r[2]), "=r"(r[3]) : "r"(addr));
}

__device__ __forceinline__ void mma16816h(float* c, const uint32_t* a,
                                          const uint32_t* b) {
    asm volatile(
        "mma.sync.aligned.m16n8k16.row.col.f32.f16.f16.f32 "
        "{%0,%1,%2,%3}, {%4,%5,%6,%7}, {%8,%9}, {%0,%1,%2,%3};"
        : "+f"(c[0]), "+f"(c[1]), "+f"(c[2]), "+f"(c[3])
        : "r"(a[0]), "r"(a[1]), "r"(a[2]), "r"(a[3]), "r"(b[0]), "r"(b[1]));
}

__device__ __forceinline__ void cp_async16(uint32_t saddr, const void* g) {
    asm volatile("cp.async.cg.shared.global [%0], [%1], 16;"
        :: "r"(saddr), "l"(g));
}
#define CP_COMMIT() asm volatile("cp.async.commit_group;" ::: "memory")
#define CP_WAIT0()  asm volatile("cp.async.wait_group 0;"  ::: "memory")

__device__ __forceinline__ void split2(float x, float y,
                                       uint32_t& h, uint32_t& l) {
    __nv_bfloat162 h2 = __floats2bfloat162_rn(x, y);
    float2 g = __bfloat1622float2(h2);
    __nv_bfloat162 l2 = __floats2bfloat162_rn(x - g.x, y - g.y);
    memcpy(&h, &h2, 4);
    memcpy(&l, &l2, 4);
}

__device__ __forceinline__ void split2h(float x, float y,
                                        uint32_t& h, uint32_t& l) {
    __half2 h2 = __floats2half2_rn(x, y);
    float2 g = __half22float2(h2);
    __half2 l2 = __floats2half2_rn(x - g.x, y - g.y);
    memcpy(&h, &h2, 4);
    memcpy(&l, &l2, 4);
}

#define SW128(o) ((o) ^ (((o) >> 3) & 0x70))

// ---------------------------------------------------------------------------
// Splits
// ---------------------------------------------------------------------------
__global__ void split_weights_kernel(const float* __restrict__ wqkv,
                                     const float* __restrict__ wp) {
    int i = blockIdx.x * blockDim.x + threadIdx.x;
    if (i < 768 * 256) {
        float f = wqkv[i];
        __nv_bfloat16 h = __float2bfloat16(f);
        g_wqkv_h[i] = h;
        g_wqkv_l[i] = __float2bfloat16(f - __bfloat162float(h));
    }
    if (i < 256 * 256) {
        float f = wp[i];
        __nv_bfloat16 h = __float2bfloat16(f);
        g_wp_h[i] = h;
        g_wp_l[i] = __float2bfloat16(f - __bfloat162float(h));
    }
}

__global__ void split_x_kernel(const float* __restrict__ x) {
    long i = (long)(blockIdx.x * blockDim.x + threadIdx.x) * 4;
    float4 v = *(const float4*)(x + i);
    uint2 h, l;
    split2(v.x, v.y, h.x, l.x);
    split2(v.z, v.w, h.y, l.y);
    *(uint2*)(g_xh + i) = h;
    *(uint2*)(g_xl + i) = l;
}

// ---------------------------------------------------------------------------
// tcgen05 feature-gated primitives + GEMM.
// ---------------------------------------------------------------------------
#define TCGEMM_OK (!defined(__CUDA_ARCH__) || defined(__CUDA_ARCH_FEAT_SM103_ALL))

// SMEM layout (bytes). Tile bases are 1024-aligned for SW128.
#define SM_TMPTR 0
#define SM_MBAR  8
#define SM_AH    1024
#define SM_AL    (SM_AH + 16384)
#define SM_BH    (SM_AL + 16384)
#define SM_BL    (SM_BH + 32768)
#define SM_TOTAL (SM_BL + 32768)          // 99328 B

// SW128 K-major descriptor (layout=2, version=1, SBO=64, LBO=1):
// verified constants from examples for 128-byte rows.
static constexpr uint64_t DESC_BASE_SW128 =
    (uint64_t(2) << 61) | (uint64_t(1) << 46) | (uint64_t(64) << 32) | (uint64_t(1) << 16);

// idesc kind::f16: F32 accum (1<<4), BF16 A (1<<7), BF16 B (1<<10),
// N=256 -> 32<<17, M=128 -> 8<<24. Same formula as verified 0x8080490 (N=32).
static constexpr uint32_t TC_IDESC =
    (1u << 4) | (1u << 7) | (1u << 10) | (32u << 17) | (8u << 24);

#if TCGEMM_OK
__device__ __forceinline__ uint32_t elect_one_pred() {
    uint32_t pred;
    asm volatile(
        "{\n\t.reg .pred p;\n\telect.sync _|p, 0xFFFFFFFF;\n\t"
        "selp.b32 %0, 1, 0, p;\n\t}" : "=r"(pred));
    return pred;
}

__device__ __forceinline__ void mma_f16_ss(uint32_t d, uint64_t a, uint64_t b,
                                           uint32_t idesc, uint32_t en) {
    asm volatile(
        "{\n\t.reg .pred p;\n\tsetp.ne.u32 p, %5, 0;\n\t"
        "tcgen05.mma.cta_group::1.kind::f16 [%0], %1, %2, %3, {%4, %4, %4, %4}, p;\n\t}"
        :: "r"(d), "l"(a), "l"(b), "r"(idesc), "r"(0u), "r"(en) : "memory");
}
#endif

__global__ __launch_bounds__(256, 2) void tc_gemm_kernel(
    const __nv_bfloat16* __restrict__ Ah, const __nv_bfloat16* __restrict__ Al,
    const __nv_bfloat16* __restrict__ Wh, const __nv_bfloat16* __restrict__ Wl,
    const float* __restrict__ bias, float* __restrict__ C, int Ntot) {
#if TCGEMM_OK
    extern __shared__ char smem[];
    const uint32_t sb = smem_u32(smem);
    const int tid  = threadIdx.x;
    const int lane = tid & 31;
    const int w    = tid >> 5;
    const long rowBase = (long)blockIdx.y * 128;
    const int  colBase = blockIdx.x * 256;

    // TMEM alloc (256 cols of fp32 D) + mbarrier init
    if (w == 0) {
        asm volatile(
            "tcgen05.alloc.cta_group::1.sync.aligned.shared::cta.b32 [%0], %1;"
            :: "r"(sb + SM_TMPTR), "r"(256u) : "memory");
        asm volatile("tcgen05.relinquish_alloc_permit.cta_group::1.sync.aligned;");
    }
    if (tid == 0)
        asm volatile("mbarrier.init.shared.b64 [%0], %1;"
            :: "r"(sb + SM_MBAR), "r"(1u) : "memory");
    __syncthreads();

    uint32_t tmem;
    asm volatile("ld.shared.b32 %0, [%1];" : "=r"(tmem) : "r"(sb + SM_TMPTR));

    int ph = 0;
    for (int c = 0; c < 4; c++) {
        // Previous chunk's MMAs must be done reading smem before overwrite.
        if (c > 0) {
            uint32_t done;
            asm volatile(
                "{\n\t.reg .pred p;\n\t"
                "mbarrier.try_wait.parity.acquire.cta.shared::cta.b64 p, [%1], %2;\n\t"
                "selp.b32 %0, 1, 0, p;\n\t}"
                : "=r"(done) : "r"(sb + SM_MBAR), "r"((uint32_t)ph) : "memory");
            if (!done) {
                asm volatile(
                    "{\n\t.reg .pred P1;\n\t"
                    "WL_%=:\n\t"
                    "mbarrier.try_wait.parity.acquire.cta.shared::cta.b64 P1, [%0], %1, 0x989680;\n\t"
                    "@P1 bra.uni WD_%=;\n\t"
                    "bra.uni WL_%=;\n\t"
                    "WD_%=:\n\t}"
                    :: "r"(sb + SM_MBAR), "r"((uint32_t)ph) : "memory");
            }
            ph ^= 1;
        }

        const int k0 = c * 64;
        // A chunk: 128 rows x 64 bf16 (128B/row, SW128) for hi and lo.
#pragma unroll
        for (int i = 0; i < 4; i++) {
            int li = tid + i * 256;          // 0..1023
            int row = li >> 3, oct = li & 7;
            uint32_t so = SW128((uint32_t)(row * 128 + oct * 16));
            long ga = (rowBase + row) * K_DIM + k0 + oct * 8;
            cp_async16(sb + SM_AH + so, Ah + ga);
            cp_async16(sb + SM_AL + so, Al + ga);
        }
        // B chunk: 256 rows x 64 bf16 for hi and lo.
#pragma unroll
        for (int i = 0; i < 8; i++) {
            int li = tid + i * 256;          // 0..2047
            int row = li >> 3, oct = li & 7;
            uint32_t so = SW128((uint32_t)(row * 128 + oct * 16));
            long gb = (long)(colBase + row) * K_DIM + k0 + oct * 8;
            cp_async16(sb + SM_BH + so, Wh + gb);
            cp_async16(sb + SM_BL + so, Wl + gb);
        }
        CP_COMMIT();
        CP_WAIT0();
        __syncthreads();
        asm volatile("fence.proxy.async.shared::cta;" ::: "memory");

        if (w == 0 && elect_one_pred()) {
            uint64_t ah = DESC_BASE_SW128 | (((uint64_t)(sb + SM_AH) >> 4) & 0x3FFF);
            uint64_t al = DESC_BASE_SW128 | (((uint64_t)(sb + SM_AL) >> 4) & 0x3FFF);
            uint64_t bh = DESC_BASE_SW128 | (((uint64_t)(sb + SM_BH) >> 4) & 0x3FFF);
            uint64_t bl = DESC_BASE_SW128 | (((uint64_t)(sb + SM_BL) >> 4) & 0x3FFF);
#pragma unroll
            for (int k = 0; k < 4; k++) {    // K=16 steps within the chunk
                uint32_t en0 = (c == 0 && k == 0) ? 0u : 1u;
                mma_f16_ss(tmem, ah + k * 2, bh + k * 2, TC_IDESC, en0);
                mma_f16_ss(tmem, ah + k * 2, bl + k * 2, TC_IDESC, 1u);
                mma_f16_ss(tmem, al + k * 2, bh + k * 2, TC_IDESC, 1u);
            }
            asm volatile(
                "tcgen05.commit.cta_group::1.mbarrier::arrive::one.shared::cluster.b64 [%0];"
                :: "r"(sb + SM_MBAR) : "memory");
        }
    }

    // Final wait: chunk-3 MMAs complete.
    {
        uint32_t done;
        asm volatile(
            "{\n\t.reg .pred p;\n\t"
            "mbarrier.try_wait.parity.acquire.cta.shared::cta.b64 p, [%1], %2;\n\t"
            "selp.b32 %0, 1, 0, p;\n\t}"
            : "=r"(done) : "r"(sb + SM_MBAR), "r"((uint32_t)ph) : "memory");
        if (!done) {
            asm volatile(
                "{\n\t.reg .pred P1;\n\t"
                "FL_%=:\n\t"
                "mbarrier.try_wait.parity.acquire.cta.shared::cta.b64 P1, [%0], %1, 0x989680;\n\t"
                "@P1 bra.uni FD_%=;\n\t"
                "bra.uni FL_%=;\n\t"
                "FD_%=:\n\t}"
                :: "r"(sb + SM_MBAR), "r"((uint32_t)ph) : "memory");
        }
    }
    asm volatile("tcgen05.fence::after_thread_sync;" ::: "memory");

    // Epilogue: 8 warps. Subpartition sp = w&3 -> rows sp*32+lane;
    // col half = (w>>2)*128 -> 4 segments of 32 cols each.
    {
        const int sp = w & 3;
        const int ch = (w >> 2) * 128;
        const long row = rowBase + sp * 32 + lane;
        float* cp = C + row * Ntot + colBase + ch;
#pragma unroll
        for (int seg = 0; seg < 4; seg++) {
            uint32_t r[32];
            asm volatile(
                "tcgen05.ld.sync.aligned.32x32b.x32.b32 "
                "{%0, %1, %2, %3, %4, %5, %6, %7, "
                " %8, %9, %10, %11, %12, %13, %14, %15, "
                " %16, %17, %18, %19, %20, %21, %22, %23, "
                " %24, %25, %26, %27, %28, %29, %30, %31}, [%32];"
                : "=r"(r[0]),  "=r"(r[1]),  "=r"(r[2]),  "=r"(r[3]),
                  "=r"(r[4]),  "=r"(r[5]),  "=r"(r[6]),  "=r"(r[7]),
                  "=r"(r[8]),  "=r"(r[9]),  "=r"(r[10]), "=r"(r[11]),
                  "=r"(r[12]), "=r"(r[13]), "=r"(r[14]), "=r"(r[15]),
                  "=r"(r[16]), "=r"(r[17]), "=r"(r[18]), "=r"(r[19]),
                  "=r"(r[20]), "=r"(r[21]), "=r"(r[22]), "=r"(r[23]),
                  "=r"(r[24]), "=r"(r[25]), "=r"(r[26]), "=r"(r[27]),
                  "=r"(r[28]), "=r"(r[29]), "=r"(r[30]), "=r"(r[31])
                : "r"(tmem + ch + seg * 32));
            asm volatile("tcgen05.wait::ld.sync.aligned;" ::: "memory");
#pragma unroll
            for (int j = 0; j < 8; j++) {
                float4 bv = __ldg((const float4*)(bias + colBase + ch + seg * 32 + j * 4));
                float4 o;
                o.x = __uint_as_float(r[j * 4 + 0]) + bv.x;
                o.y = __uint_as_float(r[j * 4 + 1]) + bv.y;
                o.z = __uint_as_float(r[j * 4 + 2]) + bv.z;
                o.w = __uint_as_float(r[j * 4 + 3]) + bv.w;
                *(float4*)(cp + seg * 32 + j * 4) = o;
            }
        }
    }
    __syncthreads();
    if (tid == 0)
        asm volatile("mbarrier.inval.shared.b64 [%0];" :: "r"(sb + SM_MBAR) : "memory");
    if (w == 0)
        asm volatile("tcgen05.dealloc.cta_group::1.sync.aligned.b32 %0, %1;"
            :: "r"(tmem), "r"(256u));
#endif  // TCGEMM_OK
}

// ---------------------------------------------------------------------------
// Tensor-core window attention (unchanged from R10 passing kernel).
// ---------------------------------------------------------------------------
#define QK_STR 40
#define VT_STR 72

__global__ __launch_bounds__(128) void window_attn_kernel(
    const float* __restrict__ qkv, const float* __restrict__ bias_table,
    __nv_bfloat16* __restrict__ yh, __nv_bfloat16* __restrict__ yl) {
    const int head = blockIdx.x & 7;
    const int wi   = blockIdx.x >> 3;
    const int bimg = wi >> 10;
    const int widx = wi & 1023;
    const int wr   = widx >> 5;
    const int wc   = widx & 31;

    __shared__ __half qh_s[64 * QK_STR];
    __shared__ __half ql_s[64 * QK_STR];
    __shared__ __half kh_s[64 * QK_STR];
    __shared__ __half kl_s[64 * QK_STR];
    __shared__ __half vh_s[32 * VT_STR];
    __shared__ __half vl_s[32 * VT_STR];
    __shared__ float  bias_s[225];

    const int tid  = threadIdx.x;
    const int lane = tid & 31;
    const int w    = tid >> 5;

    for (int i = tid; i < 225; i += 128) bias_s[i] = bias_table[i * 8 + head];

    const float scale = 0.17677669529663687f;   // 1/sqrt(32)

#pragma unroll
    for (int r = 0; r < 4; r++) {
        int q   = tid + r * 128;
        int tok = q >> 3;
        int dq  = (q & 7) * 4;
        long row = (long)bimg * 65536 + (long)(wr * 8 + (tok >> 3)) * 256 + wc * 8 + (tok & 7);
        const float* base = qkv + row * 768 + head * 32 + dq;
        float4 vq = *(const float4*)(base);
        float4 vk = *(const float4*)(base + 256);
        float4 vv = *(const float4*)(base + 512);
        uint32_t h0, l0, h1, l1;
        split2h(vq.x * scale, vq.y * scale, h0, l0);
        split2h(vq.z * scale, vq.w * scale, h1, l1);
        *(uint32_t*)&qh_s[tok * QK_STR + dq]     = h0;
        *(uint32_t*)&qh_s[tok * QK_STR + dq + 2] = h1;
        *(uint32_t*)&ql_s[tok * QK_STR + dq]     = l0;
        *(uint32_t*)&ql_s[tok * QK_STR + dq + 2] = l1;
        split2h(vk.x, vk.y, h0, l0);
        split2h(vk.z, vk.w, h1, l1);
        *(uint32_t*)&kh_s[tok * QK_STR + dq]     = h0;
        *(uint32_t*)&kh_s[tok * QK_STR + dq + 2] = h1;
        *(uint32_t*)&kl_s[tok * QK_STR + dq]     = l0;
        *(uint32_t*)&kl_s[tok * QK_STR + dq + 2] = l1;
        float vf[4] = {vv.x, vv.y, vv.z, vv.w};
#pragma unroll
        for (int j = 0; j < 4; j++) {
            __half hv = __float2half_rn(vf[j]);
            __half lv = __float2half_rn(vf[j] - __half2float(hv));
            vh_s[(dq + j) * VT_STR + tok] = hv;
            vl_s[(dq + j) * VT_STR + tok] = lv;
        }
    }
    __syncthreads();

    const int a_r = lane & 15;
    const int a_c = (lane >> 4) * 8;
    const int b_n = (lane & 7) + ((lane >> 4) << 3);
    const int b_k = ((lane >> 3) & 1) * 8;

    const uint32_t qh_b = smem_u32(qh_s), ql_b = smem_u32(ql_s);
    const uint32_t kh_b = smem_u32(kh_s), kl_b = smem_u32(kl_s);
    const uint32_t vh_b = smem_u32(vh_s), vl_b = smem_u32(vl_s);

    const int wrow = w * 16;

    uint32_t qhf[2][4], qlf[2][4];
#pragma unroll
    for (int ks = 0; ks < 2; ks++) {
        uint32_t off = (uint32_t)(((wrow + a_r) * QK_STR + ks * 16 + a_c) * 2);
        ldsm_x4(qhf[ks], qh_b + off);
        ldsm_x4(qlf[ks], ql_b + off);
    }

    float sacc[8][4];
#pragma unroll
    for (int nt = 0; nt < 8; nt++)
#pragma unroll
        for (int j = 0; j < 4; j++) sacc[nt][j] = 0.0f;

#pragma unroll
    for (int nt2 = 0; nt2 < 4; nt2++) {
#pragma unroll
        for (int ks = 0; ks < 2; ks++) {
            uint32_t off = (uint32_t)(((nt2 * 16 + b_n) * QK_STR + ks * 16 + b_k) * 2);
            uint32_t khf[4], klf[4];
            ldsm_x4(khf, kh_b + off);
            ldsm_x4(klf, kl_b + off);
            mma16816h(sacc[nt2 * 2],     qhf[ks], khf);
            mma16816h(sacc[nt2 * 2 + 1], qhf[ks], khf + 2);
            mma16816h(sacc[nt2 * 2],     qhf[ks], klf);
            mma16816h(sacc[nt2 * 2 + 1], qhf[ks], klf + 2);
            mma16816h(sacc[nt2 * 2],     qlf[ks], khf);
            mma16816h(sacc[nt2 * 2 + 1], qlf[ks], khf + 2);
        }
    }

    const int fr  = lane >> 2;
    const int fc  = (lane & 3) * 2;
    const int qi0 = wrow + fr;
    const int qi1 = qi0 + 8;

    float m0 = -1e30f, m1 = -1e30f;
#pragma unroll
    for (int nt = 0; nt < 8; nt++) {
        int ki = nt * 8 + fc;
        int q0r = qi0 >> 3, q0c = qi0 & 7, q1r = qi1 >> 3, q1c = qi1 & 7;
        int k0r = ki >> 3,  k0c = ki & 7,  k1r = (ki + 1) >> 3, k1c = (ki + 1) & 7;
        sacc[nt][0] += bias_s[(q0r - k0r + 7) * 15 + (q0c - k0c + 7)];
        sacc[nt][1] += bias_s[(q0r - k1r + 7) * 15 + (q0c - k1c + 7)];
        sacc[nt][2] += bias_s[(q1r - k0r + 7) * 15 + (q1c - k0c + 7)];
        sacc[nt][3] += bias_s[(q1r - k1r + 7) * 15 + (q1c - k1c + 7)];
        m0 = fmaxf(m0, fmaxf(sacc[nt][0], sacc[nt][1]));
        m1 = fmaxf(m1, fmaxf(sacc[nt][2], sacc[nt][3]));
    }
    m0 = fmaxf(m0, __shfl_xor_sync(0xffffffffu, m0, 1));
    m0 = fmaxf(m0, __shfl_xor_sync(0xffffffffu, m0, 2));
    m1 = fmaxf(m1, __shfl_xor_sync(0xffffffffu, m1, 1));
    m1 = fmaxf(m1, __shfl_xor_sync(0xffffffffu, m1, 2));

    float s0 = 0.0f, s1 = 0.0f;
#pragma unroll
    for (int nt = 0; nt < 8; nt++) {
        sacc[nt][0] = __expf(sacc[nt][0] - m0);
        sacc[nt][1] = __expf(sacc[nt][1] - m0);
        sacc[nt][2] = __expf(sacc[nt][2] - m1);
        sacc[nt][3] = __expf(sacc[nt][3] - m1);
        s0 += sacc[nt][0] + sacc[nt][1];
        s1 += sacc[nt][2] + sacc[nt][3];
    }
    s0 += __shfl_xor_sync(0xffffffffu, s0, 1);
    s0 += __shfl_xor_sync(0xffffffffu, s0, 2);
    s1 += __shfl_xor_sync(0xffffffffu, s1, 1);
    s1 += __shfl_xor_sync(0xffffffffu, s1, 2);
    const float inv0 = 1.0f / s0;
    const float inv1 = 1.0f / s1;

    uint32_t phf[4][4], plf[4][4];
#pragma unroll
    for (int kk = 0; kk < 4; kk++) {
        const int t0 = kk * 2, t1 = kk * 2 + 1;
        split2h(sacc[t0][0] * inv0, sacc[t0][1] * inv0, phf[kk][0], plf[kk][0]);
        split2h(sacc[t0][2] * inv1, sacc[t0][3] * inv1, phf[kk][1], plf[kk][1]);
        split2h(sacc[t1][0] * inv0, sacc[t1][1] * inv0, phf[kk][2], plf[kk][2]);
        split2h(sacc[t1][2] * inv1, sacc[t1][3] * inv1, phf[kk][3], plf[kk][3]);
    }

    float oacc[4][4];
#pragma unroll
    for (int nt = 0; nt < 4; nt++)
#pragma unroll
        for (int j = 0; j < 4; j++) oacc[nt][j] = 0.0f;

#pragma unroll
    for (int kk = 0; kk < 4; kk++) {
#pragma unroll
        for (int nt2 = 0; nt2 < 2; nt2++) {
            uint32_t off = (uint32_t)(((nt2 * 16 + b_n) * VT_STR + kk * 16 + b_k) * 2);
            uint32_t vhf[4], vlf[4];
            ldsm_x4(vhf, vh_b + off);
            ldsm_x4(vlf, vl_b + off);
            mma16816h(oacc[nt2 * 2],     phf[kk], vhf);
            mma16816h(oacc[nt2 * 2 + 1], phf[kk], vhf + 2);
            mma16816h(oacc[nt2 * 2],     phf[kk], vlf);
            mma16816h(oacc[nt2 * 2 + 1], phf[kk], vlf + 2);
            mma16816h(oacc[nt2 * 2],     plf[kk], vhf);
            mma16816h(oacc[nt2 * 2 + 1], plf[kk], vhf + 2);
        }
    }

    {
        long row0 = (long)bimg * 65536 + (long)(wr * 8 + (qi0 >> 3)) * 256 + wc * 8 + (qi0 & 7);
        long row1 = (long)bimg * 65536 + (long)(wr * 8 + (qi1 >> 3)) * 256 + wc * 8 + (qi1 & 7);
#pragma unroll
        for (int nt = 0; nt < 4; nt++) {
            int d = nt * 8 + fc;
            long off0 = row0 * 256 + head * 32 + d;
            long off1 = row1 * 256 + head * 32 + d;
            uint32_t hq, lq;
            split2(oacc[nt][0], oacc[nt][1], hq, lq);
            *(uint32_t*)(yh + off0) = hq;
            *(uint32_t*)(yl + off0) = lq;
            split2(oacc[nt][2], oacc[nt][3], hq, lq);
            *(uint32_t*)(yh + off1) = hq;
            *(uint32_t*)(yl + off1) = lq;
        }
    }
}

extern "C" void kernel_launch(void* const* d_in, const int* in_sizes, int n_in,
                              void* d_out, int out_size) {
    const float* x          = (const float*)d_in[0];
    const float* wqkv_w     = (const float*)d_in[3];
    const float* wqkv_b     = (const float*)d_in[4];
    const float* wp_w       = (const float*)d_in[5];
    const float* wp_b       = (const float*)d_in[6];
    const float* bias_table = (const float*)d_in[7];
    float* out = (float*)d_out;

    const int M = in_sizes[0] / K_DIM;         // 131072 rows

    float* qkv_ptr;
    __nv_bfloat16 *xh, *xl, *yh, *yl, *wqh, *wql, *wph, *wpl;
    cudaGetSymbolAddress((void**)&qkv_ptr, g_qkv);
    cudaGetSymbolAddress((void**)&xh, g_xh);
    cudaGetSymbolAddress((void**)&xl, g_xl);
    cudaGetSymbolAddress((void**)&yh, g_yh);
    cudaGetSymbolAddress((void**)&yl, g_yl);
    cudaGetSymbolAddress((void**)&wqh, g_wqkv_h);
    cudaGetSymbolAddress((void**)&wql, g_wqkv_l);
    cudaGetSymbolAddress((void**)&wph, g_wp_h);
    cudaGetSymbolAddress((void**)&wpl, g_wp_l);

    cudaFuncSetAttribute(tc_gemm_kernel,
                         cudaFuncAttributeMaxDynamicSharedMemorySize, SM_TOTAL);

    // 0) splits
    split_weights_kernel<<<768, 256>>>(wqkv_w, wp_w);
    split_x_kernel<<<(M * K_DIM) / (4 * 256), 256>>>(x);

    // 1) QKV projection: [M,256] @ [768,256]^T + b -> [M,768]
    {
        dim3 grid(3, M / 128);
        tc_gemm_kernel<<<grid, 256, SM_TOTAL>>>(xh, xl, wqh, wql, wqkv_b,
                                                qkv_ptr, 768);
    }

    // 2) Window attention (tensor cores; writes y split into bf16 hi/lo)
    {
        int nblocks = (M / 65536) * 1024 * 8;
        window_attn_kernel<<<nblocks, 128>>>(qkv_ptr, bias_table, yh, yl);
    }

    // 3) Output projection: [M,256] @ [256,256]^T + b -> [M,256]
    {
        dim3 grid(1, M / 128);
        tc_gemm_kernel<<<grid, 256, SM_TOTAL>>>(yh, yl, wph, wpl, wp_b,
                                                out, 256);
    }
}